// round 12
// baseline (speedup 1.0000x reference)
#include <cuda_runtime.h>
#include <cuda_bf16.h>
#include <cuda_fp16.h>
#include <cstdint>
#include <cstddef>

// ---------------- problem constants ----------------
#define B_    4
#define N_X   4096
#define M_LAT 512
#define D_IN  768
#define D_LAT 1024
#define D_INR 1024
#define HEADS 16
#define DH    64
#define L_TOT (N_X + M_LAT)   // 4608

// ---------------- scratch (no allocs allowed) ----------------
__device__ __half g_xn_h [(size_t)B_ * N_X  * D_IN ];
__device__ __half g_ln_h [(size_t)B_ * M_LAT * D_LAT];
__device__ __half g_att_h[(size_t)B_ * M_LAT * D_INR];
__device__ __half g_wq_h [(size_t)D_INR * D_LAT],      g_wq_l [(size_t)D_INR * D_LAT];
__device__ __half g_wkv_h[(size_t)2 * D_INR * D_IN],   g_wkv_l[(size_t)2 * D_INR * D_IN];
__device__ __half g_wlkv_h[(size_t)2 * D_INR * D_LAT], g_wlkv_l[(size_t)2 * D_INR * D_LAT];
__device__ __half g_wo_h [(size_t)D_LAT * D_INR],      g_wo_l [(size_t)D_LAT * D_INR];
__device__ __half g_Kh[(size_t)B_ * L_TOT * D_INR], g_Kl[(size_t)B_ * L_TOT * D_INR];
__device__ __half g_Vh[(size_t)B_ * L_TOT * D_INR], g_Vl[(size_t)B_ * L_TOT * D_INR];
__device__ __half g_Qh[(size_t)B_ * M_LAT * D_INR], g_Ql[(size_t)B_ * M_LAT * D_INR];

__device__ __forceinline__ uint32_t smem_u32(const void* p) {
    uint32_t a;
    asm("{ .reg .u64 t; cvta.to.shared.u64 t, %1; cvt.u32.u64 %0, t; }" : "=r"(a) : "l"(p));
    return a;
}
__device__ __forceinline__ uint32_t pack_h(__half a, __half b) {
    return ((uint32_t)__half_as_ushort(b) << 16) | __half_as_ushort(a);
}

#define LDMX4(r0_, r1_, r2_, r3_, addr_) \
    asm volatile("ldmatrix.sync.aligned.m8n8.x4.shared.b16 {%0,%1,%2,%3}, [%4];" \
        : "=r"(r0_), "=r"(r1_), "=r"(r2_), "=r"(r3_) : "r"(addr_))
#define LDMX4T(r0_, r1_, r2_, r3_, addr_) \
    asm volatile("ldmatrix.sync.aligned.m8n8.x4.trans.shared.b16 {%0,%1,%2,%3}, [%4];" \
        : "=r"(r0_), "=r"(r1_), "=r"(r2_), "=r"(r3_) : "r"(addr_))
#define MMA_F16(c_, a_, b0_, b1_) \
    asm volatile("mma.sync.aligned.m16n8k16.row.col.f32.f16.f16.f32 " \
        "{%0,%1,%2,%3}, {%4,%5,%6,%7}, {%8,%9}, {%0,%1,%2,%3};" \
        : "+f"((c_)[0]), "+f"((c_)[1]), "+f"((c_)[2]), "+f"((c_)[3]) \
        : "r"((a_)[0]), "r"((a_)[1]), "r"((a_)[2]), "r"((a_)[3]), "r"(b0_), "r"(b1_))
#define CP_ASYNC8(dst_, src_) \
    asm volatile("cp.async.ca.shared.global [%0], [%1], 8;" :: "r"(dst_), "l"(src_) : "memory")
#define CP_ASYNC16(dst_, src_) \
    asm volatile("cp.async.cg.shared.global [%0], [%1], 16;" :: "r"(dst_), "l"(src_) : "memory")
#define CP_COMMIT() asm volatile("cp.async.commit_group;" ::: "memory")
#define CP_WAIT(n_)  asm volatile("cp.async.wait_group %0;" :: "n"(n_) : "memory")

// =======================================================================
// fp16 2-product GEMM, cp.async 4-stage; copies issued BEFORE the MMA
// block each iteration (full-iteration prefetch lead).
// =======================================================================
#define LDSB 40
#define GT_BYTES (128 * LDSB * 2)
#define STAGE_BYTES (3 * GT_BYTES)
#define NSTAGE 4
#define GEMM_SMEM (NSTAGE * STAGE_BYTES)

__device__ __forceinline__ void copy_stage(const __half* __restrict__ A,
                                           const __half* __restrict__ Wh,
                                           const __half* __restrict__ Wl,
                                           int K, int k0, uint32_t base, int tid) {
    const int chunk = tid & 7, row0 = tid >> 3;
    #pragma unroll
    for (int p = 0; p < 4; ++p) {
        const int r = row0 + p * 32;
        const uint32_t d = base + (uint32_t)(r * 80 + chunk * 8);
        const size_t s = (size_t)r * K + k0 + chunk * 4;
        CP_ASYNC8(d,                A + s);
        CP_ASYNC8(d + GT_BYTES,     Wh + s);
        CP_ASYNC8(d + 2 * GT_BYTES, Wl + s);
    }
}

__global__ void __launch_bounds__(256, 1) gemm_mma_kernel(
    const __half* __restrict__ A, const __half* __restrict__ Wh,
    const __half* __restrict__ Wl, const float* __restrict__ bias,
    float* __restrict__ C, const float* __restrict__ gamma,
    __half* __restrict__ P0h, __half* __restrict__ P0l,
    __half* __restrict__ P1h, __half* __restrict__ P1l,
    int M, int N, int K, int R, int roff, int mode) {
    extern __shared__ __align__(16) char gsm[];
    __shared__ float sred[8][4][2][8];
    const uint32_t u0 = smem_u32(gsm);
    const int tid = threadIdx.x;
    const int lane = tid & 31, wid = tid >> 5;
    const int warp_m = wid & 1, warp_n = wid >> 1;

    const __half* Ag  = A  + (size_t)blockIdx.y * 128 * K;
    const __half* Whg = Wh + (size_t)blockIdx.x * 128 * K;
    const __half* Wlg = Wl + (size_t)blockIdx.x * 128 * K;

    const int a_m = (lane & 7) + ((lane >> 3) & 1) * 8;
    const int a_k = (lane >> 4) * 8;
    const int b_n = (lane & 7) + (lane >> 4) * 8;
    const int b_k = ((lane >> 3) & 1) * 8;

    float acc[4][4][4];
    #pragma unroll
    for (int i = 0; i < 4; i++)
        #pragma unroll
        for (int j = 0; j < 4; j++)
            #pragma unroll
            for (int t = 0; t < 4; t++) acc[i][j][t] = 0.f;

    const int NK = K / 32;
    #pragma unroll
    for (int s = 0; s < NSTAGE - 1; ++s) {
        if (s < NK) copy_stage(Ag, Whg, Wlg, K, s * 32, u0 + s * STAGE_BYTES, tid);
        CP_COMMIT();
    }

    for (int c = 0; c < NK; ++c) {
        CP_WAIT(NSTAGE - 2);
        __syncthreads();
        // issue next copy BEFORE compute: stage (c+3)%4 was last read in iter c-1,
        // and all threads are past that compute (they reached the sync above).
        if (c + NSTAGE - 1 < NK)
            copy_stage(Ag, Whg, Wlg, K, (c + NSTAGE - 1) * 32,
                       u0 + (uint32_t)((c + NSTAGE - 1) % NSTAGE) * STAGE_BYTES, tid);
        CP_COMMIT();

        const uint32_t co = (uint32_t)(c % NSTAGE) * STAGE_BYTES;
        const uint32_t uA = u0 + co, uBh = u0 + co + GT_BYTES, uBl = u0 + co + 2 * GT_BYTES;
        #pragma unroll
        for (int ks = 0; ks < 2; ++ks) {
            uint32_t ah[4][4], bh[2][4], bl[2][4];
            #pragma unroll
            for (int mt = 0; mt < 4; ++mt) {
                uint32_t off = (uint32_t)((warp_m * 64 + mt * 16 + a_m) * LDSB + ks * 16 + a_k) * 2;
                LDMX4(ah[mt][0], ah[mt][1], ah[mt][2], ah[mt][3], uA + off);
            }
            #pragma unroll
            for (int np = 0; np < 2; ++np) {
                uint32_t off = (uint32_t)((warp_n * 32 + np * 16 + b_n) * LDSB + ks * 16 + b_k) * 2;
                LDMX4(bh[np][0], bh[np][1], bh[np][2], bh[np][3], uBh + off);
                LDMX4(bl[np][0], bl[np][1], bl[np][2], bl[np][3], uBl + off);
            }
            // h-pass then l-pass: 16 independent accumulators between dependents
            #pragma unroll
            for (int mt = 0; mt < 4; ++mt)
                #pragma unroll
                for (int nt = 0; nt < 4; ++nt) {
                    const int np = nt >> 1, sel = (nt & 1) * 2;
                    MMA_F16(acc[mt][nt], ah[mt], bh[np][sel], bh[np][sel + 1]);
                }
            #pragma unroll
            for (int mt = 0; mt < 4; ++mt)
                #pragma unroll
                for (int nt = 0; nt < 4; ++nt) {
                    const int np = nt >> 1, sel = (nt & 1) * 2;
                    MMA_F16(acc[mt][nt], ah[mt], bl[np][sel], bl[np][sel + 1]);
                }
        }
    }

    const int g = lane >> 2, c2 = (lane & 3) * 2;
    const int rowb = blockIdx.y * 128 + warp_m * 64;
    const int colb = blockIdx.x * 128 + warp_n * 32;

    if (mode == 0) {
        #pragma unroll
        for (int mt = 0; mt < 4; ++mt) {
            #pragma unroll
            for (int nt = 0; nt < 4; ++nt) {
                int row = rowb + mt * 16 + g;
                int col = colb + nt * 8 + c2;
                float b0 = 0.f, b1 = 0.f;
                if (bias) { b0 = bias[col]; b1 = bias[col + 1]; }
                *(float2*)(C + (size_t)row * N + col) =
                    make_float2(acc[mt][nt][0] + b0, acc[mt][nt][1] + b1);
                *(float2*)(C + (size_t)(row + 8) * N + col) =
                    make_float2(acc[mt][nt][2] + b0, acc[mt][nt][3] + b1);
            }
        }
        return;
    }

    const bool needNorm = (mode == 2) || (colb < 1024);
    float rr[4][2] = {{1.f,1.f},{1.f,1.f},{1.f,1.f},{1.f,1.f}};
    if (needNorm) {
        __syncthreads();
        #pragma unroll
        for (int mt = 0; mt < 4; ++mt) {
            float s0 = 0.f, s1 = 0.f;
            #pragma unroll
            for (int nt = 0; nt < 4; ++nt) {
                s0 += acc[mt][nt][0] * acc[mt][nt][0] + acc[mt][nt][1] * acc[mt][nt][1];
                s1 += acc[mt][nt][2] * acc[mt][nt][2] + acc[mt][nt][3] * acc[mt][nt][3];
            }
            s0 += __shfl_xor_sync(0xffffffffu, s0, 1);
            s0 += __shfl_xor_sync(0xffffffffu, s0, 2);
            s1 += __shfl_xor_sync(0xffffffffu, s1, 1);
            s1 += __shfl_xor_sync(0xffffffffu, s1, 2);
            if ((lane & 3) == 0) { sred[wid][mt][0][g] = s0; sred[wid][mt][1][g] = s1; }
        }
        __syncthreads();
        const int pw = wid ^ 2;
        const float sb = (mode == 2) ? 0.125f : 1.0f;
        #pragma unroll
        for (int mt = 0; mt < 4; ++mt) {
            float t0 = sred[wid][mt][0][g] + sred[pw][mt][0][g];
            float t1 = sred[wid][mt][1][g] + sred[pw][mt][1][g];
            rr[mt][0] = sb / fmaxf(sqrtf(t0) * 0.125f, 1e-8f);
            rr[mt][1] = sb / fmaxf(sqrtf(t1) * 0.125f, 1e-8f);
        }
    }

    __half *Dh, *Dl;
    int cofs;
    size_t drow_base;
    if (mode == 1) {
        if (colb < 1024) { Dh = P0h; Dl = P0l; cofs = 0; }
        else             { Dh = P1h; Dl = P1l; cofs = 1024; }
        const int b0 = rowb / R;
        drow_base = (size_t)b0 * L_TOT + roff + (rowb - b0 * R);
    } else {
        Dh = P0h; Dl = P0l; cofs = 0;
        drow_base = (size_t)rowb;
    }

    #pragma unroll
    for (int mt = 0; mt < 4; ++mt) {
        #pragma unroll
        for (int nt = 0; nt < 4; ++nt) {
            const int col = colb + nt * 8 + c2;
            float ga = 1.f, gb = 1.f;
            if (needNorm) { ga = gamma[col & 63]; gb = gamma[(col + 1) & 63]; }
            const float v0 = acc[mt][nt][0] * rr[mt][0] * ga;
            const float v1 = acc[mt][nt][1] * rr[mt][0] * gb;
            const float v2 = acc[mt][nt][2] * rr[mt][1] * ga;
            const float v3 = acc[mt][nt][3] * rr[mt][1] * gb;
            const size_t prow = drow_base + mt * 16 + g;
            const size_t d0 = prow * D_INR + (col - cofs);
            const size_t d1 = (prow + 8) * D_INR + (col - cofs);
            __half h0 = __float2half_rn(v0), h1 = __float2half_rn(v1);
            __half h2 = __float2half_rn(v2), h3 = __float2half_rn(v3);
            *(uint32_t*)(Dh + d0) = pack_h(h0, h1);
            *(uint32_t*)(Dh + d1) = pack_h(h2, h3);
            *(uint32_t*)(Dl + d0) = pack_h(__float2half_rn(v0 - __half2float(h0)),
                                           __float2half_rn(v1 - __half2float(h1)));
            *(uint32_t*)(Dl + d1) = pack_h(__float2half_rn(v2 - __half2float(h2)),
                                           __float2half_rn(v3 - __half2float(h3)));
        }
    }
}

// ---------------- weight hi/lo split ----------------
__global__ void wsplit_kernel(const float4* __restrict__ W, uint32_t* __restrict__ Wh,
                              uint32_t* __restrict__ Wl, int n4) {
    int i = blockIdx.x * blockDim.x + threadIdx.x;
    if (i >= n4) return;
    float4 v = W[i];
    __half h0 = __float2half_rn(v.x), h1 = __float2half_rn(v.y);
    __half h2 = __float2half_rn(v.z), h3 = __float2half_rn(v.w);
    __half l0 = __float2half_rn(v.x - __half2float(h0));
    __half l1 = __float2half_rn(v.y - __half2float(h1));
    __half l2 = __float2half_rn(v.z - __half2float(h2));
    __half l3 = __float2half_rn(v.w - __half2float(h3));
    Wh[i * 2]     = pack_h(h0, h1); Wh[i * 2 + 1] = pack_h(h2, h3);
    Wl[i * 2]     = pack_h(l0, l1); Wl[i * 2 + 1] = pack_h(l2, l3);
}

// ---------------- layernorm -> fp16 ----------------
__global__ void layernorm_kernel(const float* __restrict__ in, __half* __restrict__ out,
                                 const float* __restrict__ g, const float* __restrict__ b,
                                 int C) {
    const int row = blockIdx.x;
    const float* x = in + (size_t)row * C;
    __half* y = out + (size_t)row * C;
    float s = 0.f, ss = 0.f;
    for (int i = threadIdx.x; i < C; i += blockDim.x) {
        float v = x[i]; s += v; ss += v * v;
    }
    __shared__ float red[2][32];
    #pragma unroll
    for (int o = 16; o; o >>= 1) {
        s  += __shfl_xor_sync(0xffffffffu, s,  o);
        ss += __shfl_xor_sync(0xffffffffu, ss, o);
    }
    int warp = threadIdx.x >> 5, lane = threadIdx.x & 31;
    if (lane == 0) { red[0][warp] = s; red[1][warp] = ss; }
    __syncthreads();
    int nw = blockDim.x >> 5;
    if (warp == 0) {
        s  = (lane < nw) ? red[0][lane] : 0.f;
        ss = (lane < nw) ? red[1][lane] : 0.f;
        #pragma unroll
        for (int o = 16; o; o >>= 1) {
            s  += __shfl_xor_sync(0xffffffffu, s,  o);
            ss += __shfl_xor_sync(0xffffffffu, ss, o);
        }
        if (lane == 0) { red[0][0] = s; red[1][0] = ss; }
    }
    __syncthreads();
    float invC = 1.f / (float)C;
    float mu  = red[0][0] * invC;
    float var = red[1][0] * invC - mu * mu;
    float rs  = rsqrtf(var + 1e-5f);
    for (int i = threadIdx.x; i < C; i += blockDim.x)
        y[i] = __float2half_rn((x[i] - mu) * rs * g[i] + b[i]);
}

// =======================================================================
// flash attention: QTILE=64, 128 threads, 2 CTAs/SM.
// Single __syncthreads per kv tile; exact wait_group bound.
// =======================================================================
#define QTILE 64
#define LDA 72
#define AST_BYTES 37376
#define ATT_SMEM (18432 + 2 * AST_BYTES)

__device__ __forceinline__ void att_stage_copy(
    uint32_t sb, const __half* __restrict__ Kh, const __half* __restrict__ Kl,
    const __half* __restrict__ Vh, const __half* __restrict__ Vl,
    const int* __restrict__ mask, size_t grow0, int hoff,
    int in_x, int mrow0, int tid) {
    #pragma unroll
    for (int i = 0; i < 16; ++i) {
        const int plane = i >> 2;
        const int sub = ((i & 3) << 7) + tid;
        const int row = sub >> 3, ch = sub & 7;
        const __half* base = (plane == 0) ? Kh : (plane == 1) ? Kl : (plane == 2) ? Vh : Vl;
        const __half* src = base + (grow0 + row) * (size_t)D_INR + hoff + ch * 8;
        const uint32_t dst = sb + (uint32_t)(plane * 9216 + row * 144 + ch * 16);
        CP_ASYNC16(dst, src);
    }
    if (in_x && tid < 16)
        CP_ASYNC16(sb + 36864 + tid * 16, mask + mrow0 + tid * 4);
}

__global__ void __launch_bounds__(128, 2) attn_mma_kernel(
    const __half* __restrict__ Qhp, const __half* __restrict__ Qlp,
    const __half* __restrict__ Khp, const __half* __restrict__ Klp,
    const __half* __restrict__ Vhp, const __half* __restrict__ Vlp,
    const int* __restrict__ mask, __half* __restrict__ out) {
    extern __shared__ __align__(16) char asmem[];
    const uint32_t u0 = smem_u32(asmem);
    const uint32_t uQh = u0, uQl = u0 + 9216;
    const uint32_t uST = u0 + 18432;

    const int qt = blockIdx.x, h = blockIdx.y, b = blockIdx.z;
    const int tid = threadIdx.x, lane = tid & 31, wid = tid >> 5;
    const int hoff = h * DH;
    const size_t qrow0 = (size_t)(b * M_LAT + qt * QTILE);
    const size_t brow0 = (size_t)b * L_TOT;

    // Q copy (group 0), stage0 copy (group 1)
    #pragma unroll
    for (int i = 0; i < 8; ++i) {
        const int plane = i >> 2;
        const int sub = ((i & 3) << 7) + tid;
        const int row = sub >> 3, ch = sub & 7;
        const __half* src = (plane ? Qlp : Qhp) + (qrow0 + row) * (size_t)D_INR + hoff + ch * 8;
        const uint32_t dst = (plane ? uQl : uQh) + (uint32_t)(row * 144 + ch * 16);
        CP_ASYNC16(dst, src);
    }
    CP_COMMIT();
    att_stage_copy(uST, Khp, Klp, Vhp, Vlp, mask, brow0, hoff, 1, b * N_X, tid);
    CP_COMMIT();
    CP_WAIT(1);        // Q ready (stage0 may still be in flight)
    __syncthreads();

    const int a_m = (lane & 7) + ((lane >> 3) & 1) * 8;
    const int a_k = (lane >> 4) * 8;
    uint32_t qh[4][4], ql[4][4];
    #pragma unroll
    for (int kc = 0; kc < 4; ++kc) {
        uint32_t off = (uint32_t)((wid * 16 + a_m) * LDA + kc * 16 + a_k) * 2;
        LDMX4(qh[kc][0], qh[kc][1], qh[kc][2], qh[kc][3], uQh + off);
        LDMX4(ql[kc][0], ql[kc][1], ql[kc][2], ql[kc][3], uQl + off);
    }

    float m0 = -3.0e38f, m8 = -3.0e38f, l0 = 0.f, l8 = 0.f;
    float O[8][4];
    #pragma unroll
    for (int i = 0; i < 8; ++i)
        #pragma unroll
        for (int j = 0; j < 4; ++j) O[i][j] = 0.f;

    const int b_n = (lane & 7) + (lane >> 4) * 8;
    const int b_k = ((lane >> 3) & 1) * 8;
    const int v_r = a_m;
    const int v_c = (lane >> 4) * 8;
    const int cq = (lane & 3) * 2;

    const int NT = L_TOT / 64;
    for (int t = 0; t < NT; ++t) {
        const int j0 = t * 64;
        const bool in_x = (j0 < N_X);
        CP_WAIT(0);        // stage t complete (only outstanding group)
        __syncthreads();   // all warps see stage t AND are done reading buffer (t+1)&1
        if (t + 1 < NT) {
            const int j1 = j0 + 64;
            att_stage_copy(uST + (uint32_t)((t + 1) & 1) * AST_BYTES,
                           Khp, Klp, Vhp, Vlp, mask, brow0 + j1, hoff,
                           (j1 < N_X) ? 1 : 0, b * N_X + j1, tid);
            CP_COMMIT();
        }

        const uint32_t sb = uST + (uint32_t)(t & 1) * AST_BYTES;
        const uint32_t uKh = sb, uKl = sb + 9216, uVh = sb + 18432, uVl = sb + 27648;
        const int* mi = (const int*)(asmem + (18432 + (size_t)(t & 1) * AST_BYTES + 36864));

        float S[8][4];
        #pragma unroll
        for (int i = 0; i < 8; ++i) { S[i][0] = S[i][1] = S[i][2] = S[i][3] = 0.f; }
        #pragma unroll
        for (int kc = 0; kc < 4; ++kc) {
            #pragma unroll
            for (int ng = 0; ng < 4; ++ng) {
                uint32_t kh4[4], kl4[4];
                uint32_t off = (uint32_t)((ng * 16 + b_n) * LDA + kc * 16 + b_k) * 2;
                LDMX4(kh4[0], kh4[1], kh4[2], kh4[3], uKh + off);
                LDMX4(kl4[0], kl4[1], kl4[2], kl4[3], uKl + off);
                MMA_F16(S[2 * ng],     qh[kc], kh4[0], kh4[1]);
                MMA_F16(S[2 * ng + 1], qh[kc], kh4[2], kh4[3]);
                MMA_F16(S[2 * ng],     qh[kc], kl4[0], kl4[1]);
                MMA_F16(S[2 * ng + 1], qh[kc], kl4[2], kl4[3]);
                MMA_F16(S[2 * ng],     ql[kc], kh4[0], kh4[1]);
                MMA_F16(S[2 * ng + 1], ql[kc], kh4[2], kh4[3]);
            }
        }
        if (in_x) {
            #pragma unroll
            for (int nt = 0; nt < 8; ++nt) {
                float a0 = mi[nt * 8 + cq]     ? 0.f : -3.0e38f;
                float a1 = mi[nt * 8 + cq + 1] ? 0.f : -3.0e38f;
                S[nt][0] += a0; S[nt][1] += a1; S[nt][2] += a0; S[nt][3] += a1;
            }
        }
        float mx0 = -3.0e38f, mx8 = -3.0e38f;
        #pragma unroll
        for (int nt = 0; nt < 8; ++nt) {
            mx0 = fmaxf(mx0, fmaxf(S[nt][0], S[nt][1]));
            mx8 = fmaxf(mx8, fmaxf(S[nt][2], S[nt][3]));
        }
        mx0 = fmaxf(mx0, __shfl_xor_sync(0xffffffffu, mx0, 1));
        mx0 = fmaxf(mx0, __shfl_xor_sync(0xffffffffu, mx0, 2));
        mx8 = fmaxf(mx8, __shfl_xor_sync(0xffffffffu, mx8, 1));
        mx8 = fmaxf(mx8, __shfl_xor_sync(0xffffffffu, mx8, 2));
        float mn0 = fmaxf(m0, mx0), mn8 = fmaxf(m8, mx8);
        float c0r = __expf(m0 - mn0), c8r = __expf(m8 - mn8);
        m0 = mn0; m8 = mn8;
        float rs0 = 0.f, rs8 = 0.f;
        uint32_t ph[4][4];
        #pragma unroll
        for (int nt = 0; nt < 8; ++nt) {
            float p0 = __expf(S[nt][0] - m0), p1 = __expf(S[nt][1] - m0);
            float p2 = __expf(S[nt][2] - m8), p3 = __expf(S[nt][3] - m8);
            rs0 += p0 + p1; rs8 += p2 + p3;
            const int kcI = nt >> 1, ap = (nt & 1) * 2;
            ph[kcI][ap]     = pack_h(__float2half_rn(p0), __float2half_rn(p1));
            ph[kcI][ap + 1] = pack_h(__float2half_rn(p2), __float2half_rn(p3));
        }
        rs0 += __shfl_xor_sync(0xffffffffu, rs0, 1);
        rs0 += __shfl_xor_sync(0xffffffffu, rs0, 2);
        rs8 += __shfl_xor_sync(0xffffffffu, rs8, 1);
        rs8 += __shfl_xor_sync(0xffffffffu, rs8, 2);
        l0 = l0 * c0r + rs0;
        l8 = l8 * c8r + rs8;
        #pragma unroll
        for (int dt = 0; dt < 8; ++dt) {
            O[dt][0] *= c0r; O[dt][1] *= c0r;
            O[dt][2] *= c8r; O[dt][3] *= c8r;
        }
        #pragma unroll
        for (int kc = 0; kc < 4; ++kc) {
            #pragma unroll
            for (int dg = 0; dg < 4; ++dg) {
                uint32_t vh4[4], vl4[4];
                uint32_t off = (uint32_t)((kc * 16 + v_r) * LDA + dg * 16 + v_c) * 2;
                LDMX4T(vh4[0], vh4[1], vh4[2], vh4[3], uVh + off);
                LDMX4T(vl4[0], vl4[1], vl4[2], vl4[3], uVl + off);
                MMA_F16(O[2 * dg],     ph[kc], vh4[0], vh4[1]);
                MMA_F16(O[2 * dg + 1], ph[kc], vh4[2], vh4[3]);
                MMA_F16(O[2 * dg],     ph[kc], vl4[0], vl4[1]);
                MMA_F16(O[2 * dg + 1], ph[kc], vl4[2], vl4[3]);
            }
        }
    }

    const float inv0 = 1.f / l0, inv8 = 1.f / l8;
    const int g = lane >> 2;
    __half* ob = out + ((size_t)(b * M_LAT + qt * QTILE + wid * 16 + g)) * D_INR + hoff;
    #pragma unroll
    for (int dt = 0; dt < 8; ++dt) {
        int col = dt * 8 + cq;
        *(__half2*)(ob + col) = __floats2half2_rn(O[dt][0] * inv0, O[dt][1] * inv0);
        *(__half2*)(ob + (size_t)8 * D_INR + col) = __floats2half2_rn(O[dt][2] * inv8, O[dt][3] * inv8);
    }
}

// ---------------- launch ----------------
extern "C" void kernel_launch(void* const* d_in, const int* in_sizes, int n_in,
                              void* d_out, int out_size) {
    const float* x      = (const float*)d_in[0];
    const float* lat    = (const float*)d_in[1];
    const int*   mask   = (const int*)  d_in[2];
    const float* ln_x_g = (const float*)d_in[3];
    const float* ln_x_b = (const float*)d_in[4];
    const float* ln_l_g = (const float*)d_in[5];
    const float* ln_l_b = (const float*)d_in[6];
    const float* qn_g   = (const float*)d_in[7];
    const float* kn_g   = (const float*)d_in[8];
    const float* Wq     = (const float*)d_in[9];
    const float* Wkv    = (const float*)d_in[10];
    const float* Wlkv   = (const float*)d_in[11];
    const float* Wo     = (const float*)d_in[12];
    const float* bo     = (const float*)d_in[13];
    float* outp = (float*)d_out;

    __half *xnh, *lnh, *atth, *wqh, *wql, *wkvh, *wkvl, *wlkvh, *wlkvl, *woh, *wol;
    __half *Khp, *Klp, *Vhp, *Vlp, *Qhp, *Qlp;
    cudaGetSymbolAddress((void**)&xnh,  g_xn_h);
    cudaGetSymbolAddress((void**)&lnh,  g_ln_h);
    cudaGetSymbolAddress((void**)&atth, g_att_h);
    cudaGetSymbolAddress((void**)&wqh,  g_wq_h);   cudaGetSymbolAddress((void**)&wql,  g_wq_l);
    cudaGetSymbolAddress((void**)&wkvh, g_wkv_h);  cudaGetSymbolAddress((void**)&wkvl, g_wkv_l);
    cudaGetSymbolAddress((void**)&wlkvh,g_wlkv_h); cudaGetSymbolAddress((void**)&wlkvl,g_wlkv_l);
    cudaGetSymbolAddress((void**)&woh,  g_wo_h);   cudaGetSymbolAddress((void**)&wol,  g_wo_l);
    cudaGetSymbolAddress((void**)&Khp,  g_Kh);     cudaGetSymbolAddress((void**)&Klp,  g_Kl);
    cudaGetSymbolAddress((void**)&Vhp,  g_Vh);     cudaGetSymbolAddress((void**)&Vlp,  g_Vl);
    cudaGetSymbolAddress((void**)&Qhp,  g_Qh);     cudaGetSymbolAddress((void**)&Qlp,  g_Ql);

    cudaFuncSetAttribute(gemm_mma_kernel, cudaFuncAttributeMaxDynamicSharedMemorySize, GEMM_SMEM);
    cudaFuncSetAttribute(attn_mma_kernel, cudaFuncAttributeMaxDynamicSharedMemorySize, ATT_SMEM);

    cudaStream_t s2;
    cudaStreamCreateWithFlags(&s2, cudaStreamNonBlocking);
    cudaEvent_t evF, evJ;
    cudaEventCreateWithFlags(&evF, cudaEventDisableTiming);
    cudaEventCreateWithFlags(&evJ, cudaEventDisableTiming);
    cudaEventRecord(evF, 0);
    cudaStreamWaitEvent(s2, evF, 0);

    // ---- stream 0 (x branch) ----
    layernorm_kernel<<<B_ * N_X, 256>>>(x, xnh, ln_x_g, ln_x_b, D_IN);
    wsplit_kernel<<<(2 * D_INR * D_IN / 4 + 255) / 256, 256>>>(
        (const float4*)Wkv, (uint32_t*)wkvh, (uint32_t*)wkvl, 2 * D_INR * D_IN / 4);
    {
        dim3 g((2 * D_INR) / 128, (B_ * N_X) / 128);
        gemm_mma_kernel<<<g, 256, GEMM_SMEM>>>(xnh, wkvh, wkvl, nullptr, nullptr, kn_g,
                                               Khp, Klp, Vhp, Vlp,
                                               B_ * N_X, 2 * D_INR, D_IN, N_X, 0, 1);
    }

    // ---- stream s2 (lat branch) ----
    layernorm_kernel<<<B_ * M_LAT, 256, 0, s2>>>(lat, lnh, ln_l_g, ln_l_b, D_LAT);
    wsplit_kernel<<<(D_INR * D_LAT / 4 + 255) / 256, 256, 0, s2>>>(
        (const float4*)Wq, (uint32_t*)wqh, (uint32_t*)wql, D_INR * D_LAT / 4);
    wsplit_kernel<<<(2 * D_INR * D_LAT / 4 + 255) / 256, 256, 0, s2>>>(
        (const float4*)Wlkv, (uint32_t*)wlkvh, (uint32_t*)wlkvl, 2 * D_INR * D_LAT / 4);
    wsplit_kernel<<<(D_LAT * D_INR / 4 + 255) / 256, 256, 0, s2>>>(
        (const float4*)Wo, (uint32_t*)woh, (uint32_t*)wol, D_LAT * D_INR / 4);
    {
        dim3 g(D_INR / 128, (B_ * M_LAT) / 128);
        gemm_mma_kernel<<<g, 256, GEMM_SMEM, s2>>>(lnh, wqh, wql, nullptr, nullptr, qn_g,
                                                   Qhp, Qlp, nullptr, nullptr,
                                                   B_ * M_LAT, D_INR, D_LAT, M_LAT, 0, 2);
    }
    {
        dim3 g((2 * D_INR) / 128, (B_ * M_LAT) / 128);
        gemm_mma_kernel<<<g, 256, GEMM_SMEM, s2>>>(lnh, wlkvh, wlkvl, nullptr, nullptr, kn_g,
                                                   Khp, Klp, Vhp, Vlp,
                                                   B_ * M_LAT, 2 * D_INR, D_LAT, M_LAT, N_X, 1);
    }

    // ---- join ----
    cudaEventRecord(evJ, s2);
    cudaStreamWaitEvent(0, evJ, 0);

    // ---- stream 0: attention -> output projection ----
    {
        dim3 g(M_LAT / QTILE, HEADS, B_);
        attn_mma_kernel<<<g, 128, ATT_SMEM>>>(Qhp, Qlp, Khp, Klp, Vhp, Vlp, mask, atth);
    }
    {
        dim3 g(D_LAT / 128, (B_ * M_LAT) / 128);
        gemm_mma_kernel<<<g, 256, GEMM_SMEM>>>(atth, woh, wol, bo, outp, nullptr,
                                               nullptr, nullptr, nullptr, nullptr,
                                               B_ * M_LAT, D_LAT, D_INR, 0, 0, 0);
    }
}

// round 15
// speedup vs baseline: 1.0686x; 1.0686x over previous
#include <cuda_runtime.h>
#include <cuda_bf16.h>
#include <cuda_fp16.h>
#include <cstdint>
#include <cstddef>

// ---------------- problem constants ----------------
#define B_    4
#define N_X   4096
#define M_LAT 512
#define D_IN  768
#define D_LAT 1024
#define D_INR 1024
#define HEADS 16
#define DH    64
#define L_TOT (N_X + M_LAT)   // 4608

// ---------------- scratch (no allocs allowed) ----------------
__device__ __half g_xn_h [(size_t)B_ * N_X  * D_IN ];
__device__ __half g_ln_h [(size_t)B_ * M_LAT * D_LAT];
__device__ __half g_att_h[(size_t)B_ * M_LAT * D_INR];
__device__ __half g_wq_h [(size_t)D_INR * D_LAT],      g_wq_l [(size_t)D_INR * D_LAT];
__device__ __half g_wkv_h[(size_t)2 * D_INR * D_IN],   g_wkv_l[(size_t)2 * D_INR * D_IN];
__device__ __half g_wlkv_h[(size_t)2 * D_INR * D_LAT], g_wlkv_l[(size_t)2 * D_INR * D_LAT];
__device__ __half g_wo_h [(size_t)D_LAT * D_INR],      g_wo_l [(size_t)D_LAT * D_INR];
__device__ __half g_Kh[(size_t)B_ * L_TOT * D_INR], g_Kl[(size_t)B_ * L_TOT * D_INR];
__device__ __half g_Vh[(size_t)B_ * L_TOT * D_INR], g_Vl[(size_t)B_ * L_TOT * D_INR];
__device__ __half g_Qh[(size_t)B_ * M_LAT * D_INR], g_Ql[(size_t)B_ * M_LAT * D_INR];

__device__ __forceinline__ uint32_t smem_u32(const void* p) {
    uint32_t a;
    asm("{ .reg .u64 t; cvta.to.shared.u64 t, %1; cvt.u32.u64 %0, t; }" : "=r"(a) : "l"(p));
    return a;
}
__device__ __forceinline__ uint32_t pack_h(__half a, __half b) {
    return ((uint32_t)__half_as_ushort(b) << 16) | __half_as_ushort(a);
}

#define LDMX4(r0_, r1_, r2_, r3_, addr_) \
    asm volatile("ldmatrix.sync.aligned.m8n8.x4.shared.b16 {%0,%1,%2,%3}, [%4];" \
        : "=r"(r0_), "=r"(r1_), "=r"(r2_), "=r"(r3_) : "r"(addr_))
#define LDMX4T(r0_, r1_, r2_, r3_, addr_) \
    asm volatile("ldmatrix.sync.aligned.m8n8.x4.trans.shared.b16 {%0,%1,%2,%3}, [%4];" \
        : "=r"(r0_), "=r"(r1_), "=r"(r2_), "=r"(r3_) : "r"(addr_))
#define MMA_F16(c_, a_, b0_, b1_) \
    asm volatile("mma.sync.aligned.m16n8k16.row.col.f32.f16.f16.f32 " \
        "{%0,%1,%2,%3}, {%4,%5,%6,%7}, {%8,%9}, {%0,%1,%2,%3};" \
        : "+f"((c_)[0]), "+f"((c_)[1]), "+f"((c_)[2]), "+f"((c_)[3]) \
        : "r"((a_)[0]), "r"((a_)[1]), "r"((a_)[2]), "r"((a_)[3]), "r"(b0_), "r"(b1_))
#define CP_ASYNC8(dst_, src_) \
    asm volatile("cp.async.ca.shared.global [%0], [%1], 8;" :: "r"(dst_), "l"(src_) : "memory")
#define CP_ASYNC16(dst_, src_) \
    asm volatile("cp.async.cg.shared.global [%0], [%1], 16;" :: "r"(dst_), "l"(src_) : "memory")
#define CP_COMMIT() asm volatile("cp.async.commit_group;" ::: "memory")
#define CP_WAIT(n_)  asm volatile("cp.async.wait_group %0;" :: "n"(n_) : "memory")

// =======================================================================
// fp16 2-product GEMM, cp.async 4-stage, fused epilogues (R11, proven).
// =======================================================================
#define LDSB 40
#define GT_BYTES (128 * LDSB * 2)
#define STAGE_BYTES (3 * GT_BYTES)
#define NSTAGE 4
#define GEMM_SMEM (NSTAGE * STAGE_BYTES)

__device__ __forceinline__ void copy_stage(const __half* __restrict__ A,
                                           const __half* __restrict__ Wh,
                                           const __half* __restrict__ Wl,
                                           int K, int k0, uint32_t base, int tid) {
    const int chunk = tid & 7, row0 = tid >> 3;
    #pragma unroll
    for (int p = 0; p < 4; ++p) {
        const int r = row0 + p * 32;
        const uint32_t d = base + (uint32_t)(r * 80 + chunk * 8);
        const size_t s = (size_t)r * K + k0 + chunk * 4;
        CP_ASYNC8(d,                A + s);
        CP_ASYNC8(d + GT_BYTES,     Wh + s);
        CP_ASYNC8(d + 2 * GT_BYTES, Wl + s);
    }
}

__global__ void __launch_bounds__(256, 1) gemm_mma_kernel(
    const __half* __restrict__ A, const __half* __restrict__ Wh,
    const __half* __restrict__ Wl, const float* __restrict__ bias,
    float* __restrict__ C, const float* __restrict__ gamma,
    __half* __restrict__ P0h, __half* __restrict__ P0l,
    __half* __restrict__ P1h, __half* __restrict__ P1l,
    int M, int N, int K, int R, int roff, int mode) {
    extern __shared__ __align__(16) char gsm[];
    __shared__ float sred[8][4][2][8];
    const uint32_t u0 = smem_u32(gsm);
    const int tid = threadIdx.x;
    const int lane = tid & 31, wid = tid >> 5;
    const int warp_m = wid & 1, warp_n = wid >> 1;

    const __half* Ag  = A  + (size_t)blockIdx.y * 128 * K;
    const __half* Whg = Wh + (size_t)blockIdx.x * 128 * K;
    const __half* Wlg = Wl + (size_t)blockIdx.x * 128 * K;

    const int a_m = (lane & 7) + ((lane >> 3) & 1) * 8;
    const int a_k = (lane >> 4) * 8;
    const int b_n = (lane & 7) + (lane >> 4) * 8;
    const int b_k = ((lane >> 3) & 1) * 8;

    float acc[4][4][4];
    #pragma unroll
    for (int i = 0; i < 4; i++)
        #pragma unroll
        for (int j = 0; j < 4; j++)
            #pragma unroll
            for (int t = 0; t < 4; t++) acc[i][j][t] = 0.f;

    const int NK = K / 32;
    #pragma unroll
    for (int s = 0; s < NSTAGE - 1; ++s) {
        if (s < NK) copy_stage(Ag, Whg, Wlg, K, s * 32, u0 + s * STAGE_BYTES, tid);
        CP_COMMIT();
    }

    for (int c = 0; c < NK; ++c) {
        CP_WAIT(NSTAGE - 2);
        __syncthreads();
        const uint32_t co = (uint32_t)(c % NSTAGE) * STAGE_BYTES;
        const uint32_t uA = u0 + co, uBh = u0 + co + GT_BYTES, uBl = u0 + co + 2 * GT_BYTES;
        #pragma unroll
        for (int ks = 0; ks < 2; ++ks) {
            uint32_t ah[4][4], bh[2][4], bl[2][4];
            #pragma unroll
            for (int mt = 0; mt < 4; ++mt) {
                uint32_t off = (uint32_t)((warp_m * 64 + mt * 16 + a_m) * LDSB + ks * 16 + a_k) * 2;
                LDMX4(ah[mt][0], ah[mt][1], ah[mt][2], ah[mt][3], uA + off);
            }
            #pragma unroll
            for (int np = 0; np < 2; ++np) {
                uint32_t off = (uint32_t)((warp_n * 32 + np * 16 + b_n) * LDSB + ks * 16 + b_k) * 2;
                LDMX4(bh[np][0], bh[np][1], bh[np][2], bh[np][3], uBh + off);
                LDMX4(bl[np][0], bl[np][1], bl[np][2], bl[np][3], uBl + off);
            }
            // h-pass then l-pass: 16 independent accumulators between dependents
            #pragma unroll
            for (int mt = 0; mt < 4; ++mt)
                #pragma unroll
                for (int nt = 0; nt < 4; ++nt) {
                    const int np = nt >> 1, sel = (nt & 1) * 2;
                    MMA_F16(acc[mt][nt], ah[mt], bh[np][sel], bh[np][sel + 1]);
                }
            #pragma unroll
            for (int mt = 0; mt < 4; ++mt)
                #pragma unroll
                for (int nt = 0; nt < 4; ++nt) {
                    const int np = nt >> 1, sel = (nt & 1) * 2;
                    MMA_F16(acc[mt][nt], ah[mt], bl[np][sel], bl[np][sel + 1]);
                }
        }
        if (c + NSTAGE - 1 < NK)
            copy_stage(Ag, Whg, Wlg, K, (c + NSTAGE - 1) * 32,
                       u0 + (uint32_t)((c + NSTAGE - 1) % NSTAGE) * STAGE_BYTES, tid);
        CP_COMMIT();
    }

    const int g = lane >> 2, c2 = (lane & 3) * 2;
    const int rowb = blockIdx.y * 128 + warp_m * 64;
    const int colb = blockIdx.x * 128 + warp_n * 32;

    if (mode == 0) {
        #pragma unroll
        for (int mt = 0; mt < 4; ++mt) {
            #pragma unroll
            for (int nt = 0; nt < 4; ++nt) {
                int row = rowb + mt * 16 + g;
                int col = colb + nt * 8 + c2;
                float b0 = 0.f, b1 = 0.f;
                if (bias) { b0 = bias[col]; b1 = bias[col + 1]; }
                *(float2*)(C + (size_t)row * N + col) =
                    make_float2(acc[mt][nt][0] + b0, acc[mt][nt][1] + b1);
                *(float2*)(C + (size_t)(row + 8) * N + col) =
                    make_float2(acc[mt][nt][2] + b0, acc[mt][nt][3] + b1);
            }
        }
        return;
    }

    const bool needNorm = (mode == 2) || (colb < 1024);
    float rr[4][2] = {{1.f,1.f},{1.f,1.f},{1.f,1.f},{1.f,1.f}};
    if (needNorm) {
        __syncthreads();
        #pragma unroll
        for (int mt = 0; mt < 4; ++mt) {
            float s0 = 0.f, s1 = 0.f;
            #pragma unroll
            for (int nt = 0; nt < 4; ++nt) {
                s0 += acc[mt][nt][0] * acc[mt][nt][0] + acc[mt][nt][1] * acc[mt][nt][1];
                s1 += acc[mt][nt][2] * acc[mt][nt][2] + acc[mt][nt][3] * acc[mt][nt][3];
            }
            s0 += __shfl_xor_sync(0xffffffffu, s0, 1);
            s0 += __shfl_xor_sync(0xffffffffu, s0, 2);
            s1 += __shfl_xor_sync(0xffffffffu, s1, 1);
            s1 += __shfl_xor_sync(0xffffffffu, s1, 2);
            if ((lane & 3) == 0) { sred[wid][mt][0][g] = s0; sred[wid][mt][1][g] = s1; }
        }
        __syncthreads();
        const int pw = wid ^ 2;
        const float sb = (mode == 2) ? 0.125f : 1.0f;
        #pragma unroll
        for (int mt = 0; mt < 4; ++mt) {
            float t0 = sred[wid][mt][0][g] + sred[pw][mt][0][g];
            float t1 = sred[wid][mt][1][g] + sred[pw][mt][1][g];
            rr[mt][0] = sb / fmaxf(sqrtf(t0) * 0.125f, 1e-8f);
            rr[mt][1] = sb / fmaxf(sqrtf(t1) * 0.125f, 1e-8f);
        }
    }

    __half *Dh, *Dl;
    int cofs;
    size_t drow_base;
    if (mode == 1) {
        if (colb < 1024) { Dh = P0h; Dl = P0l; cofs = 0; }
        else             { Dh = P1h; Dl = P1l; cofs = 1024; }
        const int b0 = rowb / R;
        drow_base = (size_t)b0 * L_TOT + roff + (rowb - b0 * R);
    } else {
        Dh = P0h; Dl = P0l; cofs = 0;
        drow_base = (size_t)rowb;
    }

    #pragma unroll
    for (int mt = 0; mt < 4; ++mt) {
        #pragma unroll
        for (int nt = 0; nt < 4; ++nt) {
            const int col = colb + nt * 8 + c2;
            float ga = 1.f, gb = 1.f;
            if (needNorm) { ga = gamma[col & 63]; gb = gamma[(col + 1) & 63]; }
            const float v0 = acc[mt][nt][0] * rr[mt][0] * ga;
            const float v1 = acc[mt][nt][1] * rr[mt][0] * gb;
            const float v2 = acc[mt][nt][2] * rr[mt][1] * ga;
            const float v3 = acc[mt][nt][3] * rr[mt][1] * gb;
            const size_t prow = drow_base + mt * 16 + g;
            const size_t d0 = prow * D_INR + (col - cofs);
            const size_t d1 = (prow + 8) * D_INR + (col - cofs);
            __half h0 = __float2half_rn(v0), h1 = __float2half_rn(v1);
            __half h2 = __float2half_rn(v2), h3 = __float2half_rn(v3);
            *(uint32_t*)(Dh + d0) = pack_h(h0, h1);
            *(uint32_t*)(Dh + d1) = pack_h(h2, h3);
            *(uint32_t*)(Dl + d0) = pack_h(__float2half_rn(v0 - __half2float(h0)),
                                           __float2half_rn(v1 - __half2float(h1)));
            *(uint32_t*)(Dl + d1) = pack_h(__float2half_rn(v2 - __half2float(h2)),
                                           __float2half_rn(v3 - __half2float(h3)));
        }
    }
}

// ---------------- weight hi/lo split ----------------
__global__ void wsplit_kernel(const float4* __restrict__ W, uint32_t* __restrict__ Wh,
                              uint32_t* __restrict__ Wl, int n4) {
    int i = blockIdx.x * blockDim.x + threadIdx.x;
    if (i >= n4) return;
    float4 v = W[i];
    __half h0 = __float2half_rn(v.x), h1 = __float2half_rn(v.y);
    __half h2 = __float2half_rn(v.z), h3 = __float2half_rn(v.w);
    __half l0 = __float2half_rn(v.x - __half2float(h0));
    __half l1 = __float2half_rn(v.y - __half2float(h1));
    __half l2 = __float2half_rn(v.z - __half2float(h2));
    __half l3 = __float2half_rn(v.w - __half2float(h3));
    Wh[i * 2]     = pack_h(h0, h1); Wh[i * 2 + 1] = pack_h(h2, h3);
    Wl[i * 2]     = pack_h(l0, l1); Wl[i * 2 + 1] = pack_h(l2, l3);
}

// ---------------- layernorm -> fp16 ----------------
__global__ void layernorm_kernel(const float* __restrict__ in, __half* __restrict__ out,
                                 const float* __restrict__ g, const float* __restrict__ b,
                                 int C) {
    const int row = blockIdx.x;
    const float* x = in + (size_t)row * C;
    __half* y = out + (size_t)row * C;
    float s = 0.f, ss = 0.f;
    for (int i = threadIdx.x; i < C; i += blockDim.x) {
        float v = x[i]; s += v; ss += v * v;
    }
    __shared__ float red[2][32];
    #pragma unroll
    for (int o = 16; o; o >>= 1) {
        s  += __shfl_xor_sync(0xffffffffu, s,  o);
        ss += __shfl_xor_sync(0xffffffffu, ss, o);
    }
    int warp = threadIdx.x >> 5, lane = threadIdx.x & 31;
    if (lane == 0) { red[0][warp] = s; red[1][warp] = ss; }
    __syncthreads();
    int nw = blockDim.x >> 5;
    if (warp == 0) {
        s  = (lane < nw) ? red[0][lane] : 0.f;
        ss = (lane < nw) ? red[1][lane] : 0.f;
        #pragma unroll
        for (int o = 16; o; o >>= 1) {
            s  += __shfl_xor_sync(0xffffffffu, s,  o);
            ss += __shfl_xor_sync(0xffffffffu, ss, o);
        }
        if (lane == 0) { red[0][0] = s; red[1][0] = ss; }
    }
    __syncthreads();
    float invC = 1.f / (float)C;
    float mu  = red[0][0] * invC;
    float var = red[1][0] * invC - mu * mu;
    float rs  = rsqrtf(var + 1e-5f);
    for (int i = threadIdx.x; i < C; i += blockDim.x)
        y[i] = __float2half_rn((x[i] - mu) * rs * g[i] + b[i]);
}

// =======================================================================
// flash attention: QTILE=64, 128 threads, 2 CTAs/SM (R11 structure intact;
// only change vs R11: the two ph·Vl MMAs and the vl4 load are removed).
// =======================================================================
#define QTILE 64
#define LDA 72
#define AST_BYTES 37376
#define ATT_SMEM (18432 + 2 * AST_BYTES)

__device__ __forceinline__ void att_stage_copy(
    uint32_t sb, const __half* __restrict__ Kh, const __half* __restrict__ Kl,
    const __half* __restrict__ Vh, const __half* __restrict__ Vl,
    const int* __restrict__ mask, size_t grow0, int hoff,
    int in_x, int mrow0, int tid) {
    #pragma unroll
    for (int i = 0; i < 16; ++i) {
        const int plane = i >> 2;
        const int sub = ((i & 3) << 7) + tid;
        const int row = sub >> 3, ch = sub & 7;
        const __half* base = (plane == 0) ? Kh : (plane == 1) ? Kl : (plane == 2) ? Vh : Vl;
        const __half* src = base + (grow0 + row) * (size_t)D_INR + hoff + ch * 8;
        const uint32_t dst = sb + (uint32_t)(plane * 9216 + row * 144 + ch * 16);
        CP_ASYNC16(dst, src);
    }
    if (in_x && tid < 16)
        CP_ASYNC16(sb + 36864 + tid * 16, mask + mrow0 + tid * 4);
}

__global__ void __launch_bounds__(128, 2) attn_mma_kernel(
    const __half* __restrict__ Qhp, const __half* __restrict__ Qlp,
    const __half* __restrict__ Khp, const __half* __restrict__ Klp,
    const __half* __restrict__ Vhp, const __half* __restrict__ Vlp,
    const int* __restrict__ mask, __half* __restrict__ out) {
    extern __shared__ __align__(16) char asmem[];
    const uint32_t u0 = smem_u32(asmem);
    const uint32_t uQh = u0, uQl = u0 + 9216;
    const uint32_t uST = u0 + 18432;

    const int qt = blockIdx.x, h = blockIdx.y, b = blockIdx.z;
    const int tid = threadIdx.x, lane = tid & 31, wid = tid >> 5;
    const int hoff = h * DH;
    const size_t qrow0 = (size_t)(b * M_LAT + qt * QTILE);
    const size_t brow0 = (size_t)b * L_TOT;

    #pragma unroll
    for (int i = 0; i < 8; ++i) {
        const int plane = i >> 2;
        const int sub = ((i & 3) << 7) + tid;
        const int row = sub >> 3, ch = sub & 7;
        const __half* src = (plane ? Qlp : Qhp) + (qrow0 + row) * (size_t)D_INR + hoff + ch * 8;
        const uint32_t dst = (plane ? uQl : uQh) + (uint32_t)(row * 144 + ch * 16);
        CP_ASYNC16(dst, src);
    }
    CP_COMMIT();
    att_stage_copy(uST, Khp, Klp, Vhp, Vlp, mask, brow0, hoff, 1, b * N_X, tid);
    CP_COMMIT();
    CP_WAIT(1);
    __syncthreads();

    const int a_m = (lane & 7) + ((lane >> 3) & 1) * 8;
    const int a_k = (lane >> 4) * 8;
    uint32_t qh[4][4], ql[4][4];
    #pragma unroll
    for (int kc = 0; kc < 4; ++kc) {
        uint32_t off = (uint32_t)((wid * 16 + a_m) * LDA + kc * 16 + a_k) * 2;
        LDMX4(qh[kc][0], qh[kc][1], qh[kc][2], qh[kc][3], uQh + off);
        LDMX4(ql[kc][0], ql[kc][1], ql[kc][2], ql[kc][3], uQl + off);
    }

    float m0 = -3.0e38f, m8 = -3.0e38f, l0 = 0.f, l8 = 0.f;
    float O[8][4];
    #pragma unroll
    for (int i = 0; i < 8; ++i)
        #pragma unroll
        for (int j = 0; j < 4; ++j) O[i][j] = 0.f;

    const int b_n = (lane & 7) + (lane >> 4) * 8;
    const int b_k = ((lane >> 3) & 1) * 8;
    const int v_r = a_m;
    const int v_c = (lane >> 4) * 8;
    const int cq = (lane & 3) * 2;

    const int NT = L_TOT / 64;
    for (int t = 0; t < NT; ++t) {
        const int j0 = t * 64;
        const bool in_x = (j0 < N_X);
        __syncthreads();
        if (t + 1 < NT) {
            const int j1 = j0 + 64;
            att_stage_copy(uST + (uint32_t)((t + 1) & 1) * AST_BYTES,
                           Khp, Klp, Vhp, Vlp, mask, brow0 + j1, hoff,
                           (j1 < N_X) ? 1 : 0, b * N_X + j1, tid);
        }
        CP_COMMIT();
        CP_WAIT(1);
        __syncthreads();

        const uint32_t sb = uST + (uint32_t)(t & 1) * AST_BYTES;
        const uint32_t uKh = sb, uKl = sb + 9216, uVh = sb + 18432;
        const int* mi = (const int*)(asmem + (18432 + (size_t)(t & 1) * AST_BYTES + 36864));

        float S[8][4];
        #pragma unroll
        for (int i = 0; i < 8; ++i) { S[i][0] = S[i][1] = S[i][2] = S[i][3] = 0.f; }
        #pragma unroll
        for (int kc = 0; kc < 4; ++kc) {
            #pragma unroll
            for (int ng = 0; ng < 4; ++ng) {
                uint32_t kh4[4], kl4[4];
                uint32_t off = (uint32_t)((ng * 16 + b_n) * LDA + kc * 16 + b_k) * 2;
                LDMX4(kh4[0], kh4[1], kh4[2], kh4[3], uKh + off);
                LDMX4(kl4[0], kl4[1], kl4[2], kl4[3], uKl + off);
                MMA_F16(S[2 * ng],     qh[kc], kh4[0], kh4[1]);
                MMA_F16(S[2 * ng + 1], qh[kc], kh4[2], kh4[3]);
                MMA_F16(S[2 * ng],     qh[kc], kl4[0], kl4[1]);
                MMA_F16(S[2 * ng + 1], qh[kc], kl4[2], kl4[3]);
                MMA_F16(S[2 * ng],     ql[kc], kh4[0], kh4[1]);
                MMA_F16(S[2 * ng + 1], ql[kc], kh4[2], kh4[3]);
            }
        }
        if (in_x) {
            #pragma unroll
            for (int nt = 0; nt < 8; ++nt) {
                float a0 = mi[nt * 8 + cq]     ? 0.f : -3.0e38f;
                float a1 = mi[nt * 8 + cq + 1] ? 0.f : -3.0e38f;
                S[nt][0] += a0; S[nt][1] += a1; S[nt][2] += a0; S[nt][3] += a1;
            }
        }
        float mx0 = -3.0e38f, mx8 = -3.0e38f;
        #pragma unroll
        for (int nt = 0; nt < 8; ++nt) {
            mx0 = fmaxf(mx0, fmaxf(S[nt][0], S[nt][1]));
            mx8 = fmaxf(mx8, fmaxf(S[nt][2], S[nt][3]));
        }
        mx0 = fmaxf(mx0, __shfl_xor_sync(0xffffffffu, mx0, 1));
        mx0 = fmaxf(mx0, __shfl_xor_sync(0xffffffffu, mx0, 2));
        mx8 = fmaxf(mx8, __shfl_xor_sync(0xffffffffu, mx8, 1));
        mx8 = fmaxf(mx8, __shfl_xor_sync(0xffffffffu, mx8, 2));
        float mn0 = fmaxf(m0, mx0), mn8 = fmaxf(m8, mx8);
        float c0r = __expf(m0 - mn0), c8r = __expf(m8 - mn8);
        m0 = mn0; m8 = mn8;
        float rs0 = 0.f, rs8 = 0.f;
        uint32_t ph[4][4];
        #pragma unroll
        for (int nt = 0; nt < 8; ++nt) {
            float p0 = __expf(S[nt][0] - m0), p1 = __expf(S[nt][1] - m0);
            float p2 = __expf(S[nt][2] - m8), p3 = __expf(S[nt][3] - m8);
            rs0 += p0 + p1; rs8 += p2 + p3;
            const int kcI = nt >> 1, ap = (nt & 1) * 2;
            ph[kcI][ap]     = pack_h(__float2half_rn(p0), __float2half_rn(p1));
            ph[kcI][ap + 1] = pack_h(__float2half_rn(p2), __float2half_rn(p3));
        }
        rs0 += __shfl_xor_sync(0xffffffffu, rs0, 1);
        rs0 += __shfl_xor_sync(0xffffffffu, rs0, 2);
        rs8 += __shfl_xor_sync(0xffffffffu, rs8, 1);
        rs8 += __shfl_xor_sync(0xffffffffu, rs8, 2);
        l0 = l0 * c0r + rs0;
        l8 = l8 * c8r + rs8;
        #pragma unroll
        for (int dt = 0; dt < 8; ++dt) {
            O[dt][0] *= c0r; O[dt][1] *= c0r;
            O[dt][2] *= c8r; O[dt][3] *= c8r;
        }
        // O += P(h) @ Vh  — ph·Vl MMAs removed (only change vs R11)
        #pragma unroll
        for (int kc = 0; kc < 4; ++kc) {
            #pragma unroll
            for (int dg = 0; dg < 4; ++dg) {
                uint32_t vh4[4];
                uint32_t off = (uint32_t)((kc * 16 + v_r) * LDA + dg * 16 + v_c) * 2;
                LDMX4T(vh4[0], vh4[1], vh4[2], vh4[3], uVh + off);
                MMA_F16(O[2 * dg],     ph[kc], vh4[0], vh4[1]);
                MMA_F16(O[2 * dg + 1], ph[kc], vh4[2], vh4[3]);
            }
        }
    }

    const float inv0 = 1.f / l0, inv8 = 1.f / l8;
    const int g = lane >> 2;
    __half* ob = out + ((size_t)(b * M_LAT + qt * QTILE + wid * 16 + g)) * D_INR + hoff;
    #pragma unroll
    for (int dt = 0; dt < 8; ++dt) {
        int col = dt * 8 + cq;
        *(__half2*)(ob + col) = __floats2half2_rn(O[dt][0] * inv0, O[dt][1] * inv0);
        *(__half2*)(ob + (size_t)8 * D_INR + col) = __floats2half2_rn(O[dt][2] * inv8, O[dt][3] * inv8);
    }
}

// ---------------- launch ----------------
extern "C" void kernel_launch(void* const* d_in, const int* in_sizes, int n_in,
                              void* d_out, int out_size) {
    const float* x      = (const float*)d_in[0];
    const float* lat    = (const float*)d_in[1];
    const int*   mask   = (const int*)  d_in[2];
    const float* ln_x_g = (const float*)d_in[3];
    const float* ln_x_b = (const float*)d_in[4];
    const float* ln_l_g = (const float*)d_in[5];
    const float* ln_l_b = (const float*)d_in[6];
    const float* qn_g   = (const float*)d_in[7];
    const float* kn_g   = (const float*)d_in[8];
    const float* Wq     = (const float*)d_in[9];
    const float* Wkv    = (const float*)d_in[10];
    const float* Wlkv   = (const float*)d_in[11];
    const float* Wo     = (const float*)d_in[12];
    const float* bo     = (const float*)d_in[13];
    float* outp = (float*)d_out;

    __half *xnh, *lnh, *atth, *wqh, *wql, *wkvh, *wkvl, *wlkvh, *wlkvl, *woh, *wol;
    __half *Khp, *Klp, *Vhp, *Vlp, *Qhp, *Qlp;
    cudaGetSymbolAddress((void**)&xnh,  g_xn_h);
    cudaGetSymbolAddress((void**)&lnh,  g_ln_h);
    cudaGetSymbolAddress((void**)&atth, g_att_h);
    cudaGetSymbolAddress((void**)&wqh,  g_wq_h);   cudaGetSymbolAddress((void**)&wql,  g_wq_l);
    cudaGetSymbolAddress((void**)&wkvh, g_wkv_h);  cudaGetSymbolAddress((void**)&wkvl, g_wkv_l);
    cudaGetSymbolAddress((void**)&wlkvh,g_wlkv_h); cudaGetSymbolAddress((void**)&wlkvl,g_wlkv_l);
    cudaGetSymbolAddress((void**)&woh,  g_wo_h);   cudaGetSymbolAddress((void**)&wol,  g_wo_l);
    cudaGetSymbolAddress((void**)&Khp,  g_Kh);     cudaGetSymbolAddress((void**)&Klp,  g_Kl);
    cudaGetSymbolAddress((void**)&Vhp,  g_Vh);     cudaGetSymbolAddress((void**)&Vlp,  g_Vl);
    cudaGetSymbolAddress((void**)&Qhp,  g_Qh);     cudaGetSymbolAddress((void**)&Qlp,  g_Ql);

    cudaFuncSetAttribute(gemm_mma_kernel, cudaFuncAttributeMaxDynamicSharedMemorySize, GEMM_SMEM);
    cudaFuncSetAttribute(attn_mma_kernel, cudaFuncAttributeMaxDynamicSharedMemorySize, ATT_SMEM);

    cudaStream_t s2;
    cudaStreamCreateWithFlags(&s2, cudaStreamNonBlocking);
    cudaEvent_t evF, evJ;
    cudaEventCreateWithFlags(&evF, cudaEventDisableTiming);
    cudaEventCreateWithFlags(&evJ, cudaEventDisableTiming);
    cudaEventRecord(evF, 0);
    cudaStreamWaitEvent(s2, evF, 0);

    // ---- stream 0 (x branch) ----
    layernorm_kernel<<<B_ * N_X, 256>>>(x, xnh, ln_x_g, ln_x_b, D_IN);
    wsplit_kernel<<<(2 * D_INR * D_IN / 4 + 255) / 256, 256>>>(
        (const float4*)Wkv, (uint32_t*)wkvh, (uint32_t*)wkvl, 2 * D_INR * D_IN / 4);
    {
        dim3 g((2 * D_INR) / 128, (B_ * N_X) / 128);
        gemm_mma_kernel<<<g, 256, GEMM_SMEM>>>(xnh, wkvh, wkvl, nullptr, nullptr, kn_g,
                                               Khp, Klp, Vhp, Vlp,
                                               B_ * N_X, 2 * D_INR, D_IN, N_X, 0, 1);
    }

    // ---- stream s2 (lat branch) ----
    layernorm_kernel<<<B_ * M_LAT, 256, 0, s2>>>(lat, lnh, ln_l_g, ln_l_b, D_LAT);
    wsplit_kernel<<<(D_INR * D_LAT / 4 + 255) / 256, 256, 0, s2>>>(
        (const float4*)Wq, (uint32_t*)wqh, (uint32_t*)wql, D_INR * D_LAT / 4);
    wsplit_kernel<<<(2 * D_INR * D_LAT / 4 + 255) / 256, 256, 0, s2>>>(
        (const float4*)Wlkv, (uint32_t*)wlkvh, (uint32_t*)wlkvl, 2 * D_INR * D_LAT / 4);
    wsplit_kernel<<<(D_LAT * D_INR / 4 + 255) / 256, 256, 0, s2>>>(
        (const float4*)Wo, (uint32_t*)woh, (uint32_t*)wol, D_LAT * D_INR / 4);
    {
        dim3 g(D_INR / 128, (B_ * M_LAT) / 128);
        gemm_mma_kernel<<<g, 256, GEMM_SMEM, s2>>>(lnh, wqh, wql, nullptr, nullptr, qn_g,
                                                   Qhp, Qlp, nullptr, nullptr,
                                                   B_ * M_LAT, D_INR, D_LAT, M_LAT, 0, 2);
    }
    {
        dim3 g((2 * D_INR) / 128, (B_ * M_LAT) / 128);
        gemm_mma_kernel<<<g, 256, GEMM_SMEM, s2>>>(lnh, wlkvh, wlkvl, nullptr, nullptr, kn_g,
                                                   Khp, Klp, Vhp, Vlp,
                                                   B_ * M_LAT, 2 * D_INR, D_LAT, M_LAT, N_X, 1);
    }

    // ---- join ----
    cudaEventRecord(evJ, s2);
    cudaStreamWaitEvent(0, evJ, 0);

    // ---- stream 0: attention -> output projection ----
    {
        dim3 g(M_LAT / QTILE, HEADS, B_);
        attn_mma_kernel<<<g, 128, ATT_SMEM>>>(Qhp, Qlp, Khp, Klp, Vhp, Vlp, mask, atth);
    }
    {
        dim3 g(D_LAT / 128, (B_ * M_LAT) / 128);
        gemm_mma_kernel<<<g, 256, GEMM_SMEM>>>(atth, woh, wol, bo, outp, nullptr,
                                               nullptr, nullptr, nullptr, nullptr,
                                               B_ * M_LAT, D_LAT, D_INR, 0, 0, 0);
    }
}

// round 16
// speedup vs baseline: 1.1351x; 1.0622x over previous
#include <cuda_runtime.h>
#include <cuda_bf16.h>
#include <cuda_fp16.h>
#include <cstdint>
#include <cstddef>

// ---------------- problem constants ----------------
#define B_    4
#define N_X   4096
#define M_LAT 512
#define D_IN  768
#define D_LAT 1024
#define D_INR 1024
#define HEADS 16
#define DH    64
#define L_TOT (N_X + M_LAT)   // 4608

// ---------------- scratch (no allocs allowed) ----------------
__device__ __half g_xn_h [(size_t)B_ * N_X  * D_IN ];
__device__ __half g_ln_h [(size_t)B_ * M_LAT * D_LAT];
__device__ __half g_att_h[(size_t)B_ * M_LAT * D_INR];
__device__ __half g_wq_h [(size_t)D_INR * D_LAT],      g_wq_l [(size_t)D_INR * D_LAT];
__device__ __half g_wkv_h[(size_t)2 * D_INR * D_IN],   g_wkv_l[(size_t)2 * D_INR * D_IN];
__device__ __half g_wlkv_h[(size_t)2 * D_INR * D_LAT], g_wlkv_l[(size_t)2 * D_INR * D_LAT];
__device__ __half g_wo_h [(size_t)D_LAT * D_INR],      g_wo_l [(size_t)D_LAT * D_INR];
__device__ __half g_Kh[(size_t)B_ * L_TOT * D_INR], g_Kl[(size_t)B_ * L_TOT * D_INR];
__device__ __half g_Vh[(size_t)B_ * L_TOT * D_INR], g_Vl[(size_t)B_ * L_TOT * D_INR];
__device__ __half g_Qh[(size_t)B_ * M_LAT * D_INR], g_Ql[(size_t)B_ * M_LAT * D_INR];

__device__ __forceinline__ uint32_t smem_u32(const void* p) {
    uint32_t a;
    asm("{ .reg .u64 t; cvta.to.shared.u64 t, %1; cvt.u32.u64 %0, t; }" : "=r"(a) : "l"(p));
    return a;
}
__device__ __forceinline__ uint32_t pack_h(__half a, __half b) {
    return ((uint32_t)__half_as_ushort(b) << 16) | __half_as_ushort(a);
}

#define LDMX4(r0_, r1_, r2_, r3_, addr_) \
    asm volatile("ldmatrix.sync.aligned.m8n8.x4.shared.b16 {%0,%1,%2,%3}, [%4];" \
        : "=r"(r0_), "=r"(r1_), "=r"(r2_), "=r"(r3_) : "r"(addr_))
#define LDMX4T(r0_, r1_, r2_, r3_, addr_) \
    asm volatile("ldmatrix.sync.aligned.m8n8.x4.trans.shared.b16 {%0,%1,%2,%3}, [%4];" \
        : "=r"(r0_), "=r"(r1_), "=r"(r2_), "=r"(r3_) : "r"(addr_))
#define MMA_F16(c_, a_, b0_, b1_) \
    asm volatile("mma.sync.aligned.m16n8k16.row.col.f32.f16.f16.f32 " \
        "{%0,%1,%2,%3}, {%4,%5,%6,%7}, {%8,%9}, {%0,%1,%2,%3};" \
        : "+f"((c_)[0]), "+f"((c_)[1]), "+f"((c_)[2]), "+f"((c_)[3]) \
        : "r"((a_)[0]), "r"((a_)[1]), "r"((a_)[2]), "r"((a_)[3]), "r"(b0_), "r"(b1_))
#define CP_ASYNC8(dst_, src_) \
    asm volatile("cp.async.ca.shared.global [%0], [%1], 8;" :: "r"(dst_), "l"(src_) : "memory")
#define CP_ASYNC16(dst_, src_) \
    asm volatile("cp.async.cg.shared.global [%0], [%1], 16;" :: "r"(dst_), "l"(src_) : "memory")
#define CP_COMMIT() asm volatile("cp.async.commit_group;" ::: "memory")
#define CP_WAIT(n_)  asm volatile("cp.async.wait_group %0;" :: "n"(n_) : "memory")

// =======================================================================
// fp16 GEMM, cp.async 4-stage, fused epilogues (R11/R15 shell).
// mode 0 (out-proj): 1-product (l-pass skipped). modes 1/2: 2-product.
// =======================================================================
#define LDSB 40
#define GT_BYTES (128 * LDSB * 2)
#define STAGE_BYTES (3 * GT_BYTES)
#define NSTAGE 4
#define GEMM_SMEM (NSTAGE * STAGE_BYTES)

__device__ __forceinline__ void copy_stage(const __half* __restrict__ A,
                                           const __half* __restrict__ Wh,
                                           const __half* __restrict__ Wl,
                                           int K, int k0, uint32_t base, int tid) {
    const int chunk = tid & 7, row0 = tid >> 3;
    #pragma unroll
    for (int p = 0; p < 4; ++p) {
        const int r = row0 + p * 32;
        const uint32_t d = base + (uint32_t)(r * 80 + chunk * 8);
        const size_t s = (size_t)r * K + k0 + chunk * 4;
        CP_ASYNC8(d,                A + s);
        CP_ASYNC8(d + GT_BYTES,     Wh + s);
        CP_ASYNC8(d + 2 * GT_BYTES, Wl + s);
    }
}

__global__ void __launch_bounds__(256, 1) gemm_mma_kernel(
    const __half* __restrict__ A, const __half* __restrict__ Wh,
    const __half* __restrict__ Wl, const float* __restrict__ bias,
    float* __restrict__ C, const float* __restrict__ gamma,
    __half* __restrict__ P0h, __half* __restrict__ P0l,
    __half* __restrict__ P1h, __half* __restrict__ P1l,
    int M, int N, int K, int R, int roff, int mode) {
    extern __shared__ __align__(16) char gsm[];
    __shared__ float sred[8][4][2][8];
    const uint32_t u0 = smem_u32(gsm);
    const int tid = threadIdx.x;
    const int lane = tid & 31, wid = tid >> 5;
    const int warp_m = wid & 1, warp_n = wid >> 1;

    const __half* Ag  = A  + (size_t)blockIdx.y * 128 * K;
    const __half* Whg = Wh + (size_t)blockIdx.x * 128 * K;
    const __half* Wlg = Wl + (size_t)blockIdx.x * 128 * K;

    const int a_m = (lane & 7) + ((lane >> 3) & 1) * 8;
    const int a_k = (lane >> 4) * 8;
    const int b_n = (lane & 7) + (lane >> 4) * 8;
    const int b_k = ((lane >> 3) & 1) * 8;

    float acc[4][4][4];
    #pragma unroll
    for (int i = 0; i < 4; i++)
        #pragma unroll
        for (int j = 0; j < 4; j++)
            #pragma unroll
            for (int t = 0; t < 4; t++) acc[i][j][t] = 0.f;

    const int NK = K / 32;
    #pragma unroll
    for (int s = 0; s < NSTAGE - 1; ++s) {
        if (s < NK) copy_stage(Ag, Whg, Wlg, K, s * 32, u0 + s * STAGE_BYTES, tid);
        CP_COMMIT();
    }

    for (int c = 0; c < NK; ++c) {
        CP_WAIT(NSTAGE - 2);
        __syncthreads();
        const uint32_t co = (uint32_t)(c % NSTAGE) * STAGE_BYTES;
        const uint32_t uA = u0 + co, uBh = u0 + co + GT_BYTES, uBl = u0 + co + 2 * GT_BYTES;
        #pragma unroll
        for (int ks = 0; ks < 2; ++ks) {
            uint32_t ah[4][4], bh[2][4], bl[2][4];
            #pragma unroll
            for (int mt = 0; mt < 4; ++mt) {
                uint32_t off = (uint32_t)((warp_m * 64 + mt * 16 + a_m) * LDSB + ks * 16 + a_k) * 2;
                LDMX4(ah[mt][0], ah[mt][1], ah[mt][2], ah[mt][3], uA + off);
            }
            #pragma unroll
            for (int np = 0; np < 2; ++np) {
                uint32_t off = (uint32_t)((warp_n * 32 + np * 16 + b_n) * LDSB + ks * 16 + b_k) * 2;
                LDMX4(bh[np][0], bh[np][1], bh[np][2], bh[np][3], uBh + off);
                LDMX4(bl[np][0], bl[np][1], bl[np][2], bl[np][3], uBl + off);
            }
            // h-pass (always)
            #pragma unroll
            for (int mt = 0; mt < 4; ++mt)
                #pragma unroll
                for (int nt = 0; nt < 4; ++nt) {
                    const int np = nt >> 1, sel = (nt & 1) * 2;
                    MMA_F16(acc[mt][nt], ah[mt], bh[np][sel], bh[np][sel + 1]);
                }
            // l-pass (skipped for mode 0: out-proj tolerates W rounding)
            if (mode != 0) {
                #pragma unroll
                for (int mt = 0; mt < 4; ++mt)
                    #pragma unroll
                    for (int nt = 0; nt < 4; ++nt) {
                        const int np = nt >> 1, sel = (nt & 1) * 2;
                        MMA_F16(acc[mt][nt], ah[mt], bl[np][sel], bl[np][sel + 1]);
                    }
            }
        }
        if (c + NSTAGE - 1 < NK)
            copy_stage(Ag, Whg, Wlg, K, (c + NSTAGE - 1) * 32,
                       u0 + (uint32_t)((c + NSTAGE - 1) % NSTAGE) * STAGE_BYTES, tid);
        CP_COMMIT();
    }

    const int g = lane >> 2, c2 = (lane & 3) * 2;
    const int rowb = blockIdx.y * 128 + warp_m * 64;
    const int colb = blockIdx.x * 128 + warp_n * 32;

    if (mode == 0) {
        #pragma unroll
        for (int mt = 0; mt < 4; ++mt) {
            #pragma unroll
            for (int nt = 0; nt < 4; ++nt) {
                int row = rowb + mt * 16 + g;
                int col = colb + nt * 8 + c2;
                float b0 = 0.f, b1 = 0.f;
                if (bias) { b0 = bias[col]; b1 = bias[col + 1]; }
                *(float2*)(C + (size_t)row * N + col) =
                    make_float2(acc[mt][nt][0] + b0, acc[mt][nt][1] + b1);
                *(float2*)(C + (size_t)(row + 8) * N + col) =
                    make_float2(acc[mt][nt][2] + b0, acc[mt][nt][3] + b1);
            }
        }
        return;
    }

    const bool needNorm = (mode == 2) || (colb < 1024);
    float rr[4][2] = {{1.f,1.f},{1.f,1.f},{1.f,1.f},{1.f,1.f}};
    if (needNorm) {
        __syncthreads();
        #pragma unroll
        for (int mt = 0; mt < 4; ++mt) {
            float s0 = 0.f, s1 = 0.f;
            #pragma unroll
            for (int nt = 0; nt < 4; ++nt) {
                s0 += acc[mt][nt][0] * acc[mt][nt][0] + acc[mt][nt][1] * acc[mt][nt][1];
                s1 += acc[mt][nt][2] * acc[mt][nt][2] + acc[mt][nt][3] * acc[mt][nt][3];
            }
            s0 += __shfl_xor_sync(0xffffffffu, s0, 1);
            s0 += __shfl_xor_sync(0xffffffffu, s0, 2);
            s1 += __shfl_xor_sync(0xffffffffu, s1, 1);
            s1 += __shfl_xor_sync(0xffffffffu, s1, 2);
            if ((lane & 3) == 0) { sred[wid][mt][0][g] = s0; sred[wid][mt][1][g] = s1; }
        }
        __syncthreads();
        const int pw = wid ^ 2;
        const float sb = (mode == 2) ? 0.125f : 1.0f;
        #pragma unroll
        for (int mt = 0; mt < 4; ++mt) {
            float t0 = sred[wid][mt][0][g] + sred[pw][mt][0][g];
            float t1 = sred[wid][mt][1][g] + sred[pw][mt][1][g];
            rr[mt][0] = sb / fmaxf(sqrtf(t0) * 0.125f, 1e-8f);
            rr[mt][1] = sb / fmaxf(sqrtf(t1) * 0.125f, 1e-8f);
        }
    }

    __half *Dh, *Dl;
    int cofs;
    size_t drow_base;
    if (mode == 1) {
        if (colb < 1024) { Dh = P0h; Dl = P0l; cofs = 0; }
        else             { Dh = P1h; Dl = P1l; cofs = 1024; }
        const int b0 = rowb / R;
        drow_base = (size_t)b0 * L_TOT + roff + (rowb - b0 * R);
    } else {
        Dh = P0h; Dl = P0l; cofs = 0;
        drow_base = (size_t)rowb;
    }

    #pragma unroll
    for (int mt = 0; mt < 4; ++mt) {
        #pragma unroll
        for (int nt = 0; nt < 4; ++nt) {
            const int col = colb + nt * 8 + c2;
            float ga = 1.f, gb = 1.f;
            if (needNorm) { ga = gamma[col & 63]; gb = gamma[(col + 1) & 63]; }
            const float v0 = acc[mt][nt][0] * rr[mt][0] * ga;
            const float v1 = acc[mt][nt][1] * rr[mt][0] * gb;
            const float v2 = acc[mt][nt][2] * rr[mt][1] * ga;
            const float v3 = acc[mt][nt][3] * rr[mt][1] * gb;
            const size_t prow = drow_base + mt * 16 + g;
            const size_t d0 = prow * D_INR + (col - cofs);
            const size_t d1 = (prow + 8) * D_INR + (col - cofs);
            __half h0 = __float2half_rn(v0), h1 = __float2half_rn(v1);
            __half h2 = __float2half_rn(v2), h3 = __float2half_rn(v3);
            *(uint32_t*)(Dh + d0) = pack_h(h0, h1);
            *(uint32_t*)(Dh + d1) = pack_h(h2, h3);
            *(uint32_t*)(Dl + d0) = pack_h(__float2half_rn(v0 - __half2float(h0)),
                                           __float2half_rn(v1 - __half2float(h1)));
            *(uint32_t*)(Dl + d1) = pack_h(__float2half_rn(v2 - __half2float(h2)),
                                           __float2half_rn(v3 - __half2float(h3)));
        }
    }
}

// ---------------- weight hi/lo split ----------------
__global__ void wsplit_kernel(const float4* __restrict__ W, uint32_t* __restrict__ Wh,
                              uint32_t* __restrict__ Wl, int n4) {
    int i = blockIdx.x * blockDim.x + threadIdx.x;
    if (i >= n4) return;
    float4 v = W[i];
    __half h0 = __float2half_rn(v.x), h1 = __float2half_rn(v.y);
    __half h2 = __float2half_rn(v.z), h3 = __float2half_rn(v.w);
    __half l0 = __float2half_rn(v.x - __half2float(h0));
    __half l1 = __float2half_rn(v.y - __half2float(h1));
    __half l2 = __float2half_rn(v.z - __half2float(h2));
    __half l3 = __float2half_rn(v.w - __half2float(h3));
    Wh[i * 2]     = pack_h(h0, h1); Wh[i * 2 + 1] = pack_h(h2, h3);
    Wl[i * 2]     = pack_h(l0, l1); Wl[i * 2 + 1] = pack_h(l2, l3);
}

// ---------------- layernorm -> fp16 ----------------
__global__ void layernorm_kernel(const float* __restrict__ in, __half* __restrict__ out,
                                 const float* __restrict__ g, const float* __restrict__ b,
                                 int C) {
    const int row = blockIdx.x;
    const float* x = in + (size_t)row * C;
    __half* y = out + (size_t)row * C;
    float s = 0.f, ss = 0.f;
    for (int i = threadIdx.x; i < C; i += blockDim.x) {
        float v = x[i]; s += v; ss += v * v;
    }
    __shared__ float red[2][32];
    #pragma unroll
    for (int o = 16; o; o >>= 1) {
        s  += __shfl_xor_sync(0xffffffffu, s,  o);
        ss += __shfl_xor_sync(0xffffffffu, ss, o);
    }
    int warp = threadIdx.x >> 5, lane = threadIdx.x & 31;
    if (lane == 0) { red[0][warp] = s; red[1][warp] = ss; }
    __syncthreads();
    int nw = blockDim.x >> 5;
    if (warp == 0) {
        s  = (lane < nw) ? red[0][lane] : 0.f;
        ss = (lane < nw) ? red[1][lane] : 0.f;
        #pragma unroll
        for (int o = 16; o; o >>= 1) {
            s  += __shfl_xor_sync(0xffffffffu, s,  o);
            ss += __shfl_xor_sync(0xffffffffu, ss, o);
        }
        if (lane == 0) { red[0][0] = s; red[1][0] = ss; }
    }
    __syncthreads();
    float invC = 1.f / (float)C;
    float mu  = red[0][0] * invC;
    float var = red[1][0] * invC - mu * mu;
    float rs  = rsqrtf(var + 1e-5f);
    for (int i = threadIdx.x; i < C; i += blockDim.x)
        y[i] = __float2half_rn((x[i] - mu) * rs * g[i] + b[i]);
}

// =======================================================================
// flash attention (R15 shell). Changes vs R15:
//   QK uses qh only: S = qh·(kh+kl)  (ql fragments/staging removed)
//   PV single product on Vh (from R15).
// =======================================================================
#define QTILE 64
#define LDA 72
#define AST_BYTES 37376
#define ATT_SMEM (18432 + 2 * AST_BYTES)

__device__ __forceinline__ void att_stage_copy(
    uint32_t sb, const __half* __restrict__ Kh, const __half* __restrict__ Kl,
    const __half* __restrict__ Vh, const __half* __restrict__ Vl,
    const int* __restrict__ mask, size_t grow0, int hoff,
    int in_x, int mrow0, int tid) {
    #pragma unroll
    for (int i = 0; i < 16; ++i) {
        const int plane = i >> 2;
        const int sub = ((i & 3) << 7) + tid;
        const int row = sub >> 3, ch = sub & 7;
        const __half* base = (plane == 0) ? Kh : (plane == 1) ? Kl : (plane == 2) ? Vh : Vl;
        const __half* src = base + (grow0 + row) * (size_t)D_INR + hoff + ch * 8;
        const uint32_t dst = sb + (uint32_t)(plane * 9216 + row * 144 + ch * 16);
        CP_ASYNC16(dst, src);
    }
    if (in_x && tid < 16)
        CP_ASYNC16(sb + 36864 + tid * 16, mask + mrow0 + tid * 4);
}

__global__ void __launch_bounds__(128, 2) attn_mma_kernel(
    const __half* __restrict__ Qhp, const __half* __restrict__ Qlp,
    const __half* __restrict__ Khp, const __half* __restrict__ Klp,
    const __half* __restrict__ Vhp, const __half* __restrict__ Vlp,
    const int* __restrict__ mask, __half* __restrict__ out) {
    extern __shared__ __align__(16) char asmem[];
    const uint32_t u0 = smem_u32(asmem);
    const uint32_t uQh = u0;
    const uint32_t uST = u0 + 18432;

    const int qt = blockIdx.x, h = blockIdx.y, b = blockIdx.z;
    const int tid = threadIdx.x, lane = tid & 31, wid = tid >> 5;
    const int hoff = h * DH;
    const size_t qrow0 = (size_t)(b * M_LAT + qt * QTILE);
    const size_t brow0 = (size_t)b * L_TOT;

    // Q stage: hi plane only
    #pragma unroll
    for (int i = 0; i < 4; ++i) {
        const int sub = (i << 7) + tid;
        const int row = sub >> 3, ch = sub & 7;
        const __half* src = Qhp + (qrow0 + row) * (size_t)D_INR + hoff + ch * 8;
        const uint32_t dst = uQh + (uint32_t)(row * 144 + ch * 16);
        CP_ASYNC16(dst, src);
    }
    CP_COMMIT();
    att_stage_copy(uST, Khp, Klp, Vhp, Vlp, mask, brow0, hoff, 1, b * N_X, tid);
    CP_COMMIT();
    CP_WAIT(1);
    __syncthreads();

    const int a_m = (lane & 7) + ((lane >> 3) & 1) * 8;
    const int a_k = (lane >> 4) * 8;
    uint32_t qh[4][4];
    #pragma unroll
    for (int kc = 0; kc < 4; ++kc) {
        uint32_t off = (uint32_t)((wid * 16 + a_m) * LDA + kc * 16 + a_k) * 2;
        LDMX4(qh[kc][0], qh[kc][1], qh[kc][2], qh[kc][3], uQh + off);
    }

    float m0 = -3.0e38f, m8 = -3.0e38f, l0 = 0.f, l8 = 0.f;
    float O[8][4];
    #pragma unroll
    for (int i = 0; i < 8; ++i)
        #pragma unroll
        for (int j = 0; j < 4; ++j) O[i][j] = 0.f;

    const int b_n = (lane & 7) + (lane >> 4) * 8;
    const int b_k = ((lane >> 3) & 1) * 8;
    const int v_r = a_m;
    const int v_c = (lane >> 4) * 8;
    const int cq = (lane & 3) * 2;

    const int NT = L_TOT / 64;
    for (int t = 0; t < NT; ++t) {
        const int j0 = t * 64;
        const bool in_x = (j0 < N_X);
        __syncthreads();
        if (t + 1 < NT) {
            const int j1 = j0 + 64;
            att_stage_copy(uST + (uint32_t)((t + 1) & 1) * AST_BYTES,
                           Khp, Klp, Vhp, Vlp, mask, brow0 + j1, hoff,
                           (j1 < N_X) ? 1 : 0, b * N_X + j1, tid);
        }
        CP_COMMIT();
        CP_WAIT(1);
        __syncthreads();

        const uint32_t sb = uST + (uint32_t)(t & 1) * AST_BYTES;
        const uint32_t uKh = sb, uKl = sb + 9216, uVh = sb + 18432;
        const int* mi = (const int*)(asmem + (18432 + (size_t)(t & 1) * AST_BYTES + 36864));

        float S[8][4];
        #pragma unroll
        for (int i = 0; i < 8; ++i) { S[i][0] = S[i][1] = S[i][2] = S[i][3] = 0.f; }
        #pragma unroll
        for (int kc = 0; kc < 4; ++kc) {
            #pragma unroll
            for (int ng = 0; ng < 4; ++ng) {
                uint32_t kh4[4], kl4[4];
                uint32_t off = (uint32_t)((ng * 16 + b_n) * LDA + kc * 16 + b_k) * 2;
                LDMX4(kh4[0], kh4[1], kh4[2], kh4[3], uKh + off);
                LDMX4(kl4[0], kl4[1], kl4[2], kl4[3], uKl + off);
                MMA_F16(S[2 * ng],     qh[kc], kh4[0], kh4[1]);
                MMA_F16(S[2 * ng + 1], qh[kc], kh4[2], kh4[3]);
                MMA_F16(S[2 * ng],     qh[kc], kl4[0], kl4[1]);
                MMA_F16(S[2 * ng + 1], qh[kc], kl4[2], kl4[3]);
            }
        }
        if (in_x) {
            #pragma unroll
            for (int nt = 0; nt < 8; ++nt) {
                float a0 = mi[nt * 8 + cq]     ? 0.f : -3.0e38f;
                float a1 = mi[nt * 8 + cq + 1] ? 0.f : -3.0e38f;
                S[nt][0] += a0; S[nt][1] += a1; S[nt][2] += a0; S[nt][3] += a1;
            }
        }
        float mx0 = -3.0e38f, mx8 = -3.0e38f;
        #pragma unroll
        for (int nt = 0; nt < 8; ++nt) {
            mx0 = fmaxf(mx0, fmaxf(S[nt][0], S[nt][1]));
            mx8 = fmaxf(mx8, fmaxf(S[nt][2], S[nt][3]));
        }
        mx0 = fmaxf(mx0, __shfl_xor_sync(0xffffffffu, mx0, 1));
        mx0 = fmaxf(mx0, __shfl_xor_sync(0xffffffffu, mx0, 2));
        mx8 = fmaxf(mx8, __shfl_xor_sync(0xffffffffu, mx8, 1));
        mx8 = fmaxf(mx8, __shfl_xor_sync(0xffffffffu, mx8, 2));
        float mn0 = fmaxf(m0, mx0), mn8 = fmaxf(m8, mx8);
        float c0r = __expf(m0 - mn0), c8r = __expf(m8 - mn8);
        m0 = mn0; m8 = mn8;
        float rs0 = 0.f, rs8 = 0.f;
        uint32_t ph[4][4];
        #pragma unroll
        for (int nt = 0; nt < 8; ++nt) {
            float p0 = __expf(S[nt][0] - m0), p1 = __expf(S[nt][1] - m0);
            float p2 = __expf(S[nt][2] - m8), p3 = __expf(S[nt][3] - m8);
            rs0 += p0 + p1; rs8 += p2 + p3;
            const int kcI = nt >> 1, ap = (nt & 1) * 2;
            ph[kcI][ap]     = pack_h(__float2half_rn(p0), __float2half_rn(p1));
            ph[kcI][ap + 1] = pack_h(__float2half_rn(p2), __float2half_rn(p3));
        }
        rs0 += __shfl_xor_sync(0xffffffffu, rs0, 1);
        rs0 += __shfl_xor_sync(0xffffffffu, rs0, 2);
        rs8 += __shfl_xor_sync(0xffffffffu, rs8, 1);
        rs8 += __shfl_xor_sync(0xffffffffu, rs8, 2);
        l0 = l0 * c0r + rs0;
        l8 = l8 * c8r + rs8;
        #pragma unroll
        for (int dt = 0; dt < 8; ++dt) {
            O[dt][0] *= c0r; O[dt][1] *= c0r;
            O[dt][2] *= c8r; O[dt][3] *= c8r;
        }
        // O += P(h) @ Vh
        #pragma unroll
        for (int kc = 0; kc < 4; ++kc) {
            #pragma unroll
            for (int dg = 0; dg < 4; ++dg) {
                uint32_t vh4[4];
                uint32_t off = (uint32_t)((kc * 16 + v_r) * LDA + dg * 16 + v_c) * 2;
                LDMX4T(vh4[0], vh4[1], vh4[2], vh4[3], uVh + off);
                MMA_F16(O[2 * dg],     ph[kc], vh4[0], vh4[1]);
                MMA_F16(O[2 * dg + 1], ph[kc], vh4[2], vh4[3]);
            }
        }
    }

    const float inv0 = 1.f / l0, inv8 = 1.f / l8;
    const int g = lane >> 2;
    __half* ob = out + ((size_t)(b * M_LAT + qt * QTILE + wid * 16 + g)) * D_INR + hoff;
    #pragma unroll
    for (int dt = 0; dt < 8; ++dt) {
        int col = dt * 8 + cq;
        *(__half2*)(ob + col) = __floats2half2_rn(O[dt][0] * inv0, O[dt][1] * inv0);
        *(__half2*)(ob + (size_t)8 * D_INR + col) = __floats2half2_rn(O[dt][2] * inv8, O[dt][3] * inv8);
    }
}

// ---------------- launch ----------------
extern "C" void kernel_launch(void* const* d_in, const int* in_sizes, int n_in,
                              void* d_out, int out_size) {
    const float* x      = (const float*)d_in[0];
    const float* lat    = (const float*)d_in[1];
    const int*   mask   = (const int*)  d_in[2];
    const float* ln_x_g = (const float*)d_in[3];
    const float* ln_x_b = (const float*)d_in[4];
    const float* ln_l_g = (const float*)d_in[5];
    const float* ln_l_b = (const float*)d_in[6];
    const float* qn_g   = (const float*)d_in[7];
    const float* kn_g   = (const float*)d_in[8];
    const float* Wq     = (const float*)d_in[9];
    const float* Wkv    = (const float*)d_in[10];
    const float* Wlkv   = (const float*)d_in[11];
    const float* Wo     = (const float*)d_in[12];
    const float* bo     = (const float*)d_in[13];
    float* outp = (float*)d_out;

    __half *xnh, *lnh, *atth, *wqh, *wql, *wkvh, *wkvl, *wlkvh, *wlkvl, *woh, *wol;
    __half *Khp, *Klp, *Vhp, *Vlp, *Qhp, *Qlp;
    cudaGetSymbolAddress((void**)&xnh,  g_xn_h);
    cudaGetSymbolAddress((void**)&lnh,  g_ln_h);
    cudaGetSymbolAddress((void**)&atth, g_att_h);
    cudaGetSymbolAddress((void**)&wqh,  g_wq_h);   cudaGetSymbolAddress((void**)&wql,  g_wq_l);
    cudaGetSymbolAddress((void**)&wkvh, g_wkv_h);  cudaGetSymbolAddress((void**)&wkvl, g_wkv_l);
    cudaGetSymbolAddress((void**)&wlkvh,g_wlkv_h); cudaGetSymbolAddress((void**)&wlkvl,g_wlkv_l);
    cudaGetSymbolAddress((void**)&woh,  g_wo_h);   cudaGetSymbolAddress((void**)&wol,  g_wo_l);
    cudaGetSymbolAddress((void**)&Khp,  g_Kh);     cudaGetSymbolAddress((void**)&Klp,  g_Kl);
    cudaGetSymbolAddress((void**)&Vhp,  g_Vh);     cudaGetSymbolAddress((void**)&Vlp,  g_Vl);
    cudaGetSymbolAddress((void**)&Qhp,  g_Qh);     cudaGetSymbolAddress((void**)&Qlp,  g_Ql);

    cudaFuncSetAttribute(gemm_mma_kernel, cudaFuncAttributeMaxDynamicSharedMemorySize, GEMM_SMEM);
    cudaFuncSetAttribute(attn_mma_kernel, cudaFuncAttributeMaxDynamicSharedMemorySize, ATT_SMEM);

    cudaStream_t s2;
    cudaStreamCreateWithFlags(&s2, cudaStreamNonBlocking);
    cudaEvent_t evF, evJ;
    cudaEventCreateWithFlags(&evF, cudaEventDisableTiming);
    cudaEventCreateWithFlags(&evJ, cudaEventDisableTiming);
    cudaEventRecord(evF, 0);
    cudaStreamWaitEvent(s2, evF, 0);

    // ---- stream 0 (x branch) ----
    layernorm_kernel<<<B_ * N_X, 256>>>(x, xnh, ln_x_g, ln_x_b, D_IN);
    wsplit_kernel<<<(2 * D_INR * D_IN / 4 + 255) / 256, 256>>>(
        (const float4*)Wkv, (uint32_t*)wkvh, (uint32_t*)wkvl, 2 * D_INR * D_IN / 4);
    {
        dim3 g((2 * D_INR) / 128, (B_ * N_X) / 128);
        gemm_mma_kernel<<<g, 256, GEMM_SMEM>>>(xnh, wkvh, wkvl, nullptr, nullptr, kn_g,
                                               Khp, Klp, Vhp, Vlp,
                                               B_ * N_X, 2 * D_INR, D_IN, N_X, 0, 1);
    }

    // ---- stream s2 (lat branch) ----
    layernorm_kernel<<<B_ * M_LAT, 256, 0, s2>>>(lat, lnh, ln_l_g, ln_l_b, D_LAT);
    wsplit_kernel<<<(D_INR * D_LAT / 4 + 255) / 256, 256, 0, s2>>>(
        (const float4*)Wq, (uint32_t*)wqh, (uint32_t*)wql, D_INR * D_LAT / 4);
    wsplit_kernel<<<(2 * D_INR * D_LAT / 4 + 255) / 256, 256, 0, s2>>>(
        (const float4*)Wlkv, (uint32_t*)wlkvh, (uint32_t*)wlkvl, 2 * D_INR * D_LAT / 4);
    wsplit_kernel<<<(D_LAT * D_INR / 4 + 255) / 256, 256, 0, s2>>>(
        (const float4*)Wo, (uint32_t*)woh, (uint32_t*)wol, D_LAT * D_INR / 4);
    {
        dim3 g(D_INR / 128, (B_ * M_LAT) / 128);
        gemm_mma_kernel<<<g, 256, GEMM_SMEM, s2>>>(lnh, wqh, wql, nullptr, nullptr, qn_g,
                                                   Qhp, Qlp, nullptr, nullptr,
                                                   B_ * M_LAT, D_INR, D_LAT, M_LAT, 0, 2);
    }
    {
        dim3 g((2 * D_INR) / 128, (B_ * M_LAT) / 128);
        gemm_mma_kernel<<<g, 256, GEMM_SMEM, s2>>>(lnh, wlkvh, wlkvl, nullptr, nullptr, kn_g,
                                                   Khp, Klp, Vhp, Vlp,
                                                   B_ * M_LAT, 2 * D_INR, D_LAT, M_LAT, N_X, 1);
    }

    // ---- join ----
    cudaEventRecord(evJ, s2);
    cudaStreamWaitEvent(0, evJ, 0);

    // ---- stream 0: attention -> output projection ----
    {
        dim3 g(M_LAT / QTILE, HEADS, B_);
        attn_mma_kernel<<<g, 128, ATT_SMEM>>>(Qhp, Qlp, Khp, Klp, Vhp, Vlp, mask, atth);
    }
    {
        dim3 g(D_LAT / 128, (B_ * M_LAT) / 128);
        gemm_mma_kernel<<<g, 256, GEMM_SMEM>>>(atth, woh, wol, bo, outp, nullptr,
                                               nullptr, nullptr, nullptr, nullptr,
                                               B_ * M_LAT, D_LAT, D_INR, 0, 0, 0);
    }
}

// round 17
// speedup vs baseline: 1.3025x; 1.1474x over previous
#include <cuda_runtime.h>
#include <cuda_bf16.h>
#include <cuda_fp16.h>
#include <cstdint>
#include <cstddef>

// ---------------- problem constants ----------------
#define B_    4
#define N_X   4096
#define M_LAT 512
#define D_IN  768
#define D_LAT 1024
#define D_INR 1024
#define HEADS 16
#define DH    64
#define L_TOT (N_X + M_LAT)   // 4608

// ---------------- scratch (no allocs allowed) ----------------
__device__ __half g_xn_h [(size_t)B_ * N_X  * D_IN ];
__device__ __half g_ln_h [(size_t)B_ * M_LAT * D_LAT];
__device__ __half g_att_h[(size_t)B_ * M_LAT * D_INR];
__device__ __half g_wq_h [(size_t)D_INR * D_LAT],      g_wq_l [(size_t)D_INR * D_LAT];
__device__ __half g_wkv_h[(size_t)2 * D_INR * D_IN],   g_wkv_l[(size_t)2 * D_INR * D_IN];
__device__ __half g_wlkv_h[(size_t)2 * D_INR * D_LAT], g_wlkv_l[(size_t)2 * D_INR * D_LAT];
__device__ __half g_wo_h [(size_t)D_LAT * D_INR],      g_wo_l [(size_t)D_LAT * D_INR];
__device__ __half g_Kh[(size_t)B_ * L_TOT * D_INR], g_Kl[(size_t)B_ * L_TOT * D_INR];
__device__ __half g_Vh[(size_t)B_ * L_TOT * D_INR], g_Vl[(size_t)B_ * L_TOT * D_INR];
__device__ __half g_Qh[(size_t)B_ * M_LAT * D_INR], g_Ql[(size_t)B_ * M_LAT * D_INR];

__device__ __forceinline__ uint32_t smem_u32(const void* p) {
    uint32_t a;
    asm("{ .reg .u64 t; cvta.to.shared.u64 t, %1; cvt.u32.u64 %0, t; }" : "=r"(a) : "l"(p));
    return a;
}
__device__ __forceinline__ uint32_t pack_h(__half a, __half b) {
    return ((uint32_t)__half_as_ushort(b) << 16) | __half_as_ushort(a);
}

#define LDMX4(r0_, r1_, r2_, r3_, addr_) \
    asm volatile("ldmatrix.sync.aligned.m8n8.x4.shared.b16 {%0,%1,%2,%3}, [%4];" \
        : "=r"(r0_), "=r"(r1_), "=r"(r2_), "=r"(r3_) : "r"(addr_))
#define LDMX4T(r0_, r1_, r2_, r3_, addr_) \
    asm volatile("ldmatrix.sync.aligned.m8n8.x4.trans.shared.b16 {%0,%1,%2,%3}, [%4];" \
        : "=r"(r0_), "=r"(r1_), "=r"(r2_), "=r"(r3_) : "r"(addr_))
#define MMA_F16(c_, a_, b0_, b1_) \
    asm volatile("mma.sync.aligned.m16n8k16.row.col.f32.f16.f16.f32 " \
        "{%0,%1,%2,%3}, {%4,%5,%6,%7}, {%8,%9}, {%0,%1,%2,%3};" \
        : "+f"((c_)[0]), "+f"((c_)[1]), "+f"((c_)[2]), "+f"((c_)[3]) \
        : "r"((a_)[0]), "r"((a_)[1]), "r"((a_)[2]), "r"((a_)[3]), "r"(b0_), "r"(b1_))
#define CP_ASYNC8(dst_, src_) \
    asm volatile("cp.async.ca.shared.global [%0], [%1], 8;" :: "r"(dst_), "l"(src_) : "memory")
#define CP_ASYNC16(dst_, src_) \
    asm volatile("cp.async.cg.shared.global [%0], [%1], 16;" :: "r"(dst_), "l"(src_) : "memory")
#define CP_COMMIT() asm volatile("cp.async.commit_group;" ::: "memory")
#define CP_WAIT(n_)  asm volatile("cp.async.wait_group %0;" :: "n"(n_) : "memory")

// =======================================================================
// fp16 GEMM, cp.async 4-stage, fused epilogues (R15/R16 shell).
// mode 2 (q): 2-product. modes 0/1: 1-product, Wl not staged/loaded.
// =======================================================================
#define LDSB 40
#define GT_BYTES (128 * LDSB * 2)
#define STAGE_BYTES (3 * GT_BYTES)
#define NSTAGE 4
#define GEMM_SMEM (NSTAGE * STAGE_BYTES)

__device__ __forceinline__ void copy_stage(const __half* __restrict__ A,
                                           const __half* __restrict__ Wh,
                                           const __half* __restrict__ Wl,
                                           int K, int k0, uint32_t base, int tid, int wl) {
    const int chunk = tid & 7, row0 = tid >> 3;
    #pragma unroll
    for (int p = 0; p < 4; ++p) {
        const int r = row0 + p * 32;
        const uint32_t d = base + (uint32_t)(r * 80 + chunk * 8);
        const size_t s = (size_t)r * K + k0 + chunk * 4;
        CP_ASYNC8(d,                A + s);
        CP_ASYNC8(d + GT_BYTES,     Wh + s);
        if (wl) CP_ASYNC8(d + 2 * GT_BYTES, Wl + s);
    }
}

__global__ void __launch_bounds__(256, 1) gemm_mma_kernel(
    const __half* __restrict__ A, const __half* __restrict__ Wh,
    const __half* __restrict__ Wl, const float* __restrict__ bias,
    float* __restrict__ C, const float* __restrict__ gamma,
    __half* __restrict__ P0h, __half* __restrict__ P0l,
    __half* __restrict__ P1h, __half* __restrict__ P1l,
    int M, int N, int K, int R, int roff, int mode) {
    extern __shared__ __align__(16) char gsm[];
    __shared__ float sred[8][4][2][8];
    const uint32_t u0 = smem_u32(gsm);
    const int tid = threadIdx.x;
    const int lane = tid & 31, wid = tid >> 5;
    const int warp_m = wid & 1, warp_n = wid >> 1;
    const int useWl = (mode == 2) ? 1 : 0;

    const __half* Ag  = A  + (size_t)blockIdx.y * 128 * K;
    const __half* Whg = Wh + (size_t)blockIdx.x * 128 * K;
    const __half* Wlg = Wl + (size_t)blockIdx.x * 128 * K;

    const int a_m = (lane & 7) + ((lane >> 3) & 1) * 8;
    const int a_k = (lane >> 4) * 8;
    const int b_n = (lane & 7) + (lane >> 4) * 8;
    const int b_k = ((lane >> 3) & 1) * 8;

    float acc[4][4][4];
    #pragma unroll
    for (int i = 0; i < 4; i++)
        #pragma unroll
        for (int j = 0; j < 4; j++)
            #pragma unroll
            for (int t = 0; t < 4; t++) acc[i][j][t] = 0.f;

    const int NK = K / 32;
    #pragma unroll
    for (int s = 0; s < NSTAGE - 1; ++s) {
        if (s < NK) copy_stage(Ag, Whg, Wlg, K, s * 32, u0 + s * STAGE_BYTES, tid, useWl);
        CP_COMMIT();
    }

    for (int c = 0; c < NK; ++c) {
        CP_WAIT(NSTAGE - 2);
        __syncthreads();
        const uint32_t co = (uint32_t)(c % NSTAGE) * STAGE_BYTES;
        const uint32_t uA = u0 + co, uBh = u0 + co + GT_BYTES, uBl = u0 + co + 2 * GT_BYTES;
        #pragma unroll
        for (int ks = 0; ks < 2; ++ks) {
            uint32_t ah[4][4], bh[2][4], bl[2][4];
            #pragma unroll
            for (int mt = 0; mt < 4; ++mt) {
                uint32_t off = (uint32_t)((warp_m * 64 + mt * 16 + a_m) * LDSB + ks * 16 + a_k) * 2;
                LDMX4(ah[mt][0], ah[mt][1], ah[mt][2], ah[mt][3], uA + off);
            }
            #pragma unroll
            for (int np = 0; np < 2; ++np) {
                uint32_t off = (uint32_t)((warp_n * 32 + np * 16 + b_n) * LDSB + ks * 16 + b_k) * 2;
                LDMX4(bh[np][0], bh[np][1], bh[np][2], bh[np][3], uBh + off);
                if (useWl) LDMX4(bl[np][0], bl[np][1], bl[np][2], bl[np][3], uBl + off);
            }
            // h-pass (always)
            #pragma unroll
            for (int mt = 0; mt < 4; ++mt)
                #pragma unroll
                for (int nt = 0; nt < 4; ++nt) {
                    const int np = nt >> 1, sel = (nt & 1) * 2;
                    MMA_F16(acc[mt][nt], ah[mt], bh[np][sel], bh[np][sel + 1]);
                }
            // l-pass (q GEMM only)
            if (useWl) {
                #pragma unroll
                for (int mt = 0; mt < 4; ++mt)
                    #pragma unroll
                    for (int nt = 0; nt < 4; ++nt) {
                        const int np = nt >> 1, sel = (nt & 1) * 2;
                        MMA_F16(acc[mt][nt], ah[mt], bl[np][sel], bl[np][sel + 1]);
                    }
            }
        }
        if (c + NSTAGE - 1 < NK)
            copy_stage(Ag, Whg, Wlg, K, (c + NSTAGE - 1) * 32,
                       u0 + (uint32_t)((c + NSTAGE - 1) % NSTAGE) * STAGE_BYTES, tid, useWl);
        CP_COMMIT();
    }

    const int g = lane >> 2, c2 = (lane & 3) * 2;
    const int rowb = blockIdx.y * 128 + warp_m * 64;
    const int colb = blockIdx.x * 128 + warp_n * 32;

    if (mode == 0) {
        #pragma unroll
        for (int mt = 0; mt < 4; ++mt) {
            #pragma unroll
            for (int nt = 0; nt < 4; ++nt) {
                int row = rowb + mt * 16 + g;
                int col = colb + nt * 8 + c2;
                float b0 = 0.f, b1 = 0.f;
                if (bias) { b0 = bias[col]; b1 = bias[col + 1]; }
                *(float2*)(C + (size_t)row * N + col) =
                    make_float2(acc[mt][nt][0] + b0, acc[mt][nt][1] + b1);
                *(float2*)(C + (size_t)(row + 8) * N + col) =
                    make_float2(acc[mt][nt][2] + b0, acc[mt][nt][3] + b1);
            }
        }
        return;
    }

    const bool needNorm = (mode == 2) || (colb < 1024);
    float rr[4][2] = {{1.f,1.f},{1.f,1.f},{1.f,1.f},{1.f,1.f}};
    if (needNorm) {
        __syncthreads();
        #pragma unroll
        for (int mt = 0; mt < 4; ++mt) {
            float s0 = 0.f, s1 = 0.f;
            #pragma unroll
            for (int nt = 0; nt < 4; ++nt) {
                s0 += acc[mt][nt][0] * acc[mt][nt][0] + acc[mt][nt][1] * acc[mt][nt][1];
                s1 += acc[mt][nt][2] * acc[mt][nt][2] + acc[mt][nt][3] * acc[mt][nt][3];
            }
            s0 += __shfl_xor_sync(0xffffffffu, s0, 1);
            s0 += __shfl_xor_sync(0xffffffffu, s0, 2);
            s1 += __shfl_xor_sync(0xffffffffu, s1, 1);
            s1 += __shfl_xor_sync(0xffffffffu, s1, 2);
            if ((lane & 3) == 0) { sred[wid][mt][0][g] = s0; sred[wid][mt][1][g] = s1; }
        }
        __syncthreads();
        const int pw = wid ^ 2;
        const float sb = (mode == 2) ? 0.125f : 1.0f;
        #pragma unroll
        for (int mt = 0; mt < 4; ++mt) {
            float t0 = sred[wid][mt][0][g] + sred[pw][mt][0][g];
            float t1 = sred[wid][mt][1][g] + sred[pw][mt][1][g];
            rr[mt][0] = sb / fmaxf(sqrtf(t0) * 0.125f, 1e-8f);
            rr[mt][1] = sb / fmaxf(sqrtf(t1) * 0.125f, 1e-8f);
        }
    }

    __half *Dh, *Dl;
    int cofs;
    size_t drow_base;
    if (mode == 1) {
        if (colb < 1024) { Dh = P0h; Dl = P0l; cofs = 0; }
        else             { Dh = P1h; Dl = P1l; cofs = 1024; }
        const int b0 = rowb / R;
        drow_base = (size_t)b0 * L_TOT + roff + (rowb - b0 * R);
    } else {
        Dh = P0h; Dl = P0l; cofs = 0;
        drow_base = (size_t)rowb;
    }

    #pragma unroll
    for (int mt = 0; mt < 4; ++mt) {
        #pragma unroll
        for (int nt = 0; nt < 4; ++nt) {
            const int col = colb + nt * 8 + c2;
            float ga = 1.f, gb = 1.f;
            if (needNorm) { ga = gamma[col & 63]; gb = gamma[(col + 1) & 63]; }
            const float v0 = acc[mt][nt][0] * rr[mt][0] * ga;
            const float v1 = acc[mt][nt][1] * rr[mt][0] * gb;
            const float v2 = acc[mt][nt][2] * rr[mt][1] * ga;
            const float v3 = acc[mt][nt][3] * rr[mt][1] * gb;
            const size_t prow = drow_base + mt * 16 + g;
            const size_t d0 = prow * D_INR + (col - cofs);
            const size_t d1 = (prow + 8) * D_INR + (col - cofs);
            __half h0 = __float2half_rn(v0), h1 = __float2half_rn(v1);
            __half h2 = __float2half_rn(v2), h3 = __float2half_rn(v3);
            *(uint32_t*)(Dh + d0) = pack_h(h0, h1);
            *(uint32_t*)(Dh + d1) = pack_h(h2, h3);
            *(uint32_t*)(Dl + d0) = pack_h(__float2half_rn(v0 - __half2float(h0)),
                                           __float2half_rn(v1 - __half2float(h1)));
            *(uint32_t*)(Dl + d1) = pack_h(__float2half_rn(v2 - __half2float(h2)),
                                           __float2half_rn(v3 - __half2float(h3)));
        }
    }
}

// ---------------- weight hi/lo split ----------------
__global__ void wsplit_kernel(const float4* __restrict__ W, uint32_t* __restrict__ Wh,
                              uint32_t* __restrict__ Wl, int n4) {
    int i = blockIdx.x * blockDim.x + threadIdx.x;
    if (i >= n4) return;
    float4 v = W[i];
    __half h0 = __float2half_rn(v.x), h1 = __float2half_rn(v.y);
    __half h2 = __float2half_rn(v.z), h3 = __float2half_rn(v.w);
    __half l0 = __float2half_rn(v.x - __half2float(h0));
    __half l1 = __float2half_rn(v.y - __half2float(h1));
    __half l2 = __float2half_rn(v.z - __half2float(h2));
    __half l3 = __float2half_rn(v.w - __half2float(h3));
    Wh[i * 2]     = pack_h(h0, h1); Wh[i * 2 + 1] = pack_h(h2, h3);
    Wl[i * 2]     = pack_h(l0, l1); Wl[i * 2 + 1] = pack_h(l2, l3);
}

// ---------------- layernorm -> fp16 ----------------
__global__ void layernorm_kernel(const float* __restrict__ in, __half* __restrict__ out,
                                 const float* __restrict__ g, const float* __restrict__ b,
                                 int C) {
    const int row = blockIdx.x;
    const float* x = in + (size_t)row * C;
    __half* y = out + (size_t)row * C;
    float s = 0.f, ss = 0.f;
    for (int i = threadIdx.x; i < C; i += blockDim.x) {
        float v = x[i]; s += v; ss += v * v;
    }
    __shared__ float red[2][32];
    #pragma unroll
    for (int o = 16; o; o >>= 1) {
        s  += __shfl_xor_sync(0xffffffffu, s,  o);
        ss += __shfl_xor_sync(0xffffffffu, ss, o);
    }
    int warp = threadIdx.x >> 5, lane = threadIdx.x & 31;
    if (lane == 0) { red[0][warp] = s; red[1][warp] = ss; }
    __syncthreads();
    int nw = blockDim.x >> 5;
    if (warp == 0) {
        s  = (lane < nw) ? red[0][lane] : 0.f;
        ss = (lane < nw) ? red[1][lane] : 0.f;
        #pragma unroll
        for (int o = 16; o; o >>= 1) {
            s  += __shfl_xor_sync(0xffffffffu, s,  o);
            ss += __shfl_xor_sync(0xffffffffu, ss, o);
        }
        if (lane == 0) { red[0][0] = s; red[1][0] = ss; }
    }
    __syncthreads();
    float invC = 1.f / (float)C;
    float mu  = red[0][0] * invC;
    float var = red[1][0] * invC - mu * mu;
    float rs  = rsqrtf(var + 1e-5f);
    for (int i = threadIdx.x; i < C; i += blockDim.x)
        y[i] = __float2half_rn((x[i] - mu) * rs * g[i] + b[i]);
}

// =======================================================================
// flash attention (R16, unchanged): QK = qh·(kh+kl), PV = P·Vh.
// =======================================================================
#define QTILE 64
#define LDA 72
#define AST_BYTES 37376
#define ATT_SMEM (18432 + 2 * AST_BYTES)

__device__ __forceinline__ void att_stage_copy(
    uint32_t sb, const __half* __restrict__ Kh, const __half* __restrict__ Kl,
    const __half* __restrict__ Vh, const __half* __restrict__ Vl,
    const int* __restrict__ mask, size_t grow0, int hoff,
    int in_x, int mrow0, int tid) {
    #pragma unroll
    for (int i = 0; i < 16; ++i) {
        const int plane = i >> 2;
        const int sub = ((i & 3) << 7) + tid;
        const int row = sub >> 3, ch = sub & 7;
        const __half* base = (plane == 0) ? Kh : (plane == 1) ? Kl : (plane == 2) ? Vh : Vl;
        const __half* src = base + (grow0 + row) * (size_t)D_INR + hoff + ch * 8;
        const uint32_t dst = sb + (uint32_t)(plane * 9216 + row * 144 + ch * 16);
        CP_ASYNC16(dst, src);
    }
    if (in_x && tid < 16)
        CP_ASYNC16(sb + 36864 + tid * 16, mask + mrow0 + tid * 4);
}

__global__ void __launch_bounds__(128, 2) attn_mma_kernel(
    const __half* __restrict__ Qhp, const __half* __restrict__ Qlp,
    const __half* __restrict__ Khp, const __half* __restrict__ Klp,
    const __half* __restrict__ Vhp, const __half* __restrict__ Vlp,
    const int* __restrict__ mask, __half* __restrict__ out) {
    extern __shared__ __align__(16) char asmem[];
    const uint32_t u0 = smem_u32(asmem);
    const uint32_t uQh = u0;
    const uint32_t uST = u0 + 18432;

    const int qt = blockIdx.x, h = blockIdx.y, b = blockIdx.z;
    const int tid = threadIdx.x, lane = tid & 31, wid = tid >> 5;
    const int hoff = h * DH;
    const size_t qrow0 = (size_t)(b * M_LAT + qt * QTILE);
    const size_t brow0 = (size_t)b * L_TOT;

    #pragma unroll
    for (int i = 0; i < 4; ++i) {
        const int sub = (i << 7) + tid;
        const int row = sub >> 3, ch = sub & 7;
        const __half* src = Qhp + (qrow0 + row) * (size_t)D_INR + hoff + ch * 8;
        const uint32_t dst = uQh + (uint32_t)(row * 144 + ch * 16);
        CP_ASYNC16(dst, src);
    }
    CP_COMMIT();
    att_stage_copy(uST, Khp, Klp, Vhp, Vlp, mask, brow0, hoff, 1, b * N_X, tid);
    CP_COMMIT();
    CP_WAIT(1);
    __syncthreads();

    const int a_m = (lane & 7) + ((lane >> 3) & 1) * 8;
    const int a_k = (lane >> 4) * 8;
    uint32_t qh[4][4];
    #pragma unroll
    for (int kc = 0; kc < 4; ++kc) {
        uint32_t off = (uint32_t)((wid * 16 + a_m) * LDA + kc * 16 + a_k) * 2;
        LDMX4(qh[kc][0], qh[kc][1], qh[kc][2], qh[kc][3], uQh + off);
    }

    float m0 = -3.0e38f, m8 = -3.0e38f, l0 = 0.f, l8 = 0.f;
    float O[8][4];
    #pragma unroll
    for (int i = 0; i < 8; ++i)
        #pragma unroll
        for (int j = 0; j < 4; ++j) O[i][j] = 0.f;

    const int b_n = (lane & 7) + (lane >> 4) * 8;
    const int b_k = ((lane >> 3) & 1) * 8;
    const int v_r = a_m;
    const int v_c = (lane >> 4) * 8;
    const int cq = (lane & 3) * 2;

    const int NT = L_TOT / 64;
    for (int t = 0; t < NT; ++t) {
        const int j0 = t * 64;
        const bool in_x = (j0 < N_X);
        __syncthreads();
        if (t + 1 < NT) {
            const int j1 = j0 + 64;
            att_stage_copy(uST + (uint32_t)((t + 1) & 1) * AST_BYTES,
                           Khp, Klp, Vhp, Vlp, mask, brow0 + j1, hoff,
                           (j1 < N_X) ? 1 : 0, b * N_X + j1, tid);
        }
        CP_COMMIT();
        CP_WAIT(1);
        __syncthreads();

        const uint32_t sb = uST + (uint32_t)(t & 1) * AST_BYTES;
        const uint32_t uKh = sb, uKl = sb + 9216, uVh = sb + 18432;
        const int* mi = (const int*)(asmem + (18432 + (size_t)(t & 1) * AST_BYTES + 36864));

        float S[8][4];
        #pragma unroll
        for (int i = 0; i < 8; ++i) { S[i][0] = S[i][1] = S[i][2] = S[i][3] = 0.f; }
        #pragma unroll
        for (int kc = 0; kc < 4; ++kc) {
            #pragma unroll
            for (int ng = 0; ng < 4; ++ng) {
                uint32_t kh4[4], kl4[4];
                uint32_t off = (uint32_t)((ng * 16 + b_n) * LDA + kc * 16 + b_k) * 2;
                LDMX4(kh4[0], kh4[1], kh4[2], kh4[3], uKh + off);
                LDMX4(kl4[0], kl4[1], kl4[2], kl4[3], uKl + off);
                MMA_F16(S[2 * ng],     qh[kc], kh4[0], kh4[1]);
                MMA_F16(S[2 * ng + 1], qh[kc], kh4[2], kh4[3]);
                MMA_F16(S[2 * ng],     qh[kc], kl4[0], kl4[1]);
                MMA_F16(S[2 * ng + 1], qh[kc], kl4[2], kl4[3]);
            }
        }
        if (in_x) {
            #pragma unroll
            for (int nt = 0; nt < 8; ++nt) {
                float a0 = mi[nt * 8 + cq]     ? 0.f : -3.0e38f;
                float a1 = mi[nt * 8 + cq + 1] ? 0.f : -3.0e38f;
                S[nt][0] += a0; S[nt][1] += a1; S[nt][2] += a0; S[nt][3] += a1;
            }
        }
        float mx0 = -3.0e38f, mx8 = -3.0e38f;
        #pragma unroll
        for (int nt = 0; nt < 8; ++nt) {
            mx0 = fmaxf(mx0, fmaxf(S[nt][0], S[nt][1]));
            mx8 = fmaxf(mx8, fmaxf(S[nt][2], S[nt][3]));
        }
        mx0 = fmaxf(mx0, __shfl_xor_sync(0xffffffffu, mx0, 1));
        mx0 = fmaxf(mx0, __shfl_xor_sync(0xffffffffu, mx0, 2));
        mx8 = fmaxf(mx8, __shfl_xor_sync(0xffffffffu, mx8, 1));
        mx8 = fmaxf(mx8, __shfl_xor_sync(0xffffffffu, mx8, 2));
        float mn0 = fmaxf(m0, mx0), mn8 = fmaxf(m8, mx8);
        float c0r = __expf(m0 - mn0), c8r = __expf(m8 - mn8);
        m0 = mn0; m8 = mn8;
        float rs0 = 0.f, rs8 = 0.f;
        uint32_t ph[4][4];
        #pragma unroll
        for (int nt = 0; nt < 8; ++nt) {
            float p0 = __expf(S[nt][0] - m0), p1 = __expf(S[nt][1] - m0);
            float p2 = __expf(S[nt][2] - m8), p3 = __expf(S[nt][3] - m8);
            rs0 += p0 + p1; rs8 += p2 + p3;
            const int kcI = nt >> 1, ap = (nt & 1) * 2;
            ph[kcI][ap]     = pack_h(__float2half_rn(p0), __float2half_rn(p1));
            ph[kcI][ap + 1] = pack_h(__float2half_rn(p2), __float2half_rn(p3));
        }
        rs0 += __shfl_xor_sync(0xffffffffu, rs0, 1);
        rs0 += __shfl_xor_sync(0xffffffffu, rs0, 2);
        rs8 += __shfl_xor_sync(0xffffffffu, rs8, 1);
        rs8 += __shfl_xor_sync(0xffffffffu, rs8, 2);
        l0 = l0 * c0r + rs0;
        l8 = l8 * c8r + rs8;
        #pragma unroll
        for (int dt = 0; dt < 8; ++dt) {
            O[dt][0] *= c0r; O[dt][1] *= c0r;
            O[dt][2] *= c8r; O[dt][3] *= c8r;
        }
        #pragma unroll
        for (int kc = 0; kc < 4; ++kc) {
            #pragma unroll
            for (int dg = 0; dg < 4; ++dg) {
                uint32_t vh4[4];
                uint32_t off = (uint32_t)((kc * 16 + v_r) * LDA + dg * 16 + v_c) * 2;
                LDMX4T(vh4[0], vh4[1], vh4[2], vh4[3], uVh + off);
                MMA_F16(O[2 * dg],     ph[kc], vh4[0], vh4[1]);
                MMA_F16(O[2 * dg + 1], ph[kc], vh4[2], vh4[3]);
            }
        }
    }

    const float inv0 = 1.f / l0, inv8 = 1.f / l8;
    const int g = lane >> 2;
    __half* ob = out + ((size_t)(b * M_LAT + qt * QTILE + wid * 16 + g)) * D_INR + hoff;
    #pragma unroll
    for (int dt = 0; dt < 8; ++dt) {
        int col = dt * 8 + cq;
        *(__half2*)(ob + col) = __floats2half2_rn(O[dt][0] * inv0, O[dt][1] * inv0);
        *(__half2*)(ob + (size_t)8 * D_INR + col) = __floats2half2_rn(O[dt][2] * inv8, O[dt][3] * inv8);
    }
}

// ---------------- launch ----------------
extern "C" void kernel_launch(void* const* d_in, const int* in_sizes, int n_in,
                              void* d_out, int out_size) {
    const float* x      = (const float*)d_in[0];
    const float* lat    = (const float*)d_in[1];
    const int*   mask   = (const int*)  d_in[2];
    const float* ln_x_g = (const float*)d_in[3];
    const float* ln_x_b = (const float*)d_in[4];
    const float* ln_l_g = (const float*)d_in[5];
    const float* ln_l_b = (const float*)d_in[6];
    const float* qn_g   = (const float*)d_in[7];
    const float* kn_g   = (const float*)d_in[8];
    const float* Wq     = (const float*)d_in[9];
    const float* Wkv    = (const float*)d_in[10];
    const float* Wlkv   = (const float*)d_in[11];
    const float* Wo     = (const float*)d_in[12];
    const float* bo     = (const float*)d_in[13];
    float* outp = (float*)d_out;

    __half *xnh, *lnh, *atth, *wqh, *wql, *wkvh, *wkvl, *wlkvh, *wlkvl, *woh, *wol;
    __half *Khp, *Klp, *Vhp, *Vlp, *Qhp, *Qlp;
    cudaGetSymbolAddress((void**)&xnh,  g_xn_h);
    cudaGetSymbolAddress((void**)&lnh,  g_ln_h);
    cudaGetSymbolAddress((void**)&atth, g_att_h);
    cudaGetSymbolAddress((void**)&wqh,  g_wq_h);   cudaGetSymbolAddress((void**)&wql,  g_wq_l);
    cudaGetSymbolAddress((void**)&wkvh, g_wkv_h);  cudaGetSymbolAddress((void**)&wkvl, g_wkv_l);
    cudaGetSymbolAddress((void**)&wlkvh,g_wlkv_h); cudaGetSymbolAddress((void**)&wlkvl,g_wlkv_l);
    cudaGetSymbolAddress((void**)&woh,  g_wo_h);   cudaGetSymbolAddress((void**)&wol,  g_wo_l);
    cudaGetSymbolAddress((void**)&Khp,  g_Kh);     cudaGetSymbolAddress((void**)&Klp,  g_Kl);
    cudaGetSymbolAddress((void**)&Vhp,  g_Vh);     cudaGetSymbolAddress((void**)&Vlp,  g_Vl);
    cudaGetSymbolAddress((void**)&Qhp,  g_Qh);     cudaGetSymbolAddress((void**)&Qlp,  g_Ql);

    cudaFuncSetAttribute(gemm_mma_kernel, cudaFuncAttributeMaxDynamicSharedMemorySize, GEMM_SMEM);
    cudaFuncSetAttribute(attn_mma_kernel, cudaFuncAttributeMaxDynamicSharedMemorySize, ATT_SMEM);

    cudaStream_t s2;
    cudaStreamCreateWithFlags(&s2, cudaStreamNonBlocking);
    cudaEvent_t evF, evJ;
    cudaEventCreateWithFlags(&evF, cudaEventDisableTiming);
    cudaEventCreateWithFlags(&evJ, cudaEventDisableTiming);
    cudaEventRecord(evF, 0);
    cudaStreamWaitEvent(s2, evF, 0);

    // ---- stream 0 (x branch) ----
    layernorm_kernel<<<B_ * N_X, 256>>>(x, xnh, ln_x_g, ln_x_b, D_IN);
    wsplit_kernel<<<(2 * D_INR * D_IN / 4 + 255) / 256, 256>>>(
        (const float4*)Wkv, (uint32_t*)wkvh, (uint32_t*)wkvl, 2 * D_INR * D_IN / 4);
    {
        dim3 g((2 * D_INR) / 128, (B_ * N_X) / 128);
        gemm_mma_kernel<<<g, 256, GEMM_SMEM>>>(xnh, wkvh, wkvl, nullptr, nullptr, kn_g,
                                               Khp, Klp, Vhp, Vlp,
                                               B_ * N_X, 2 * D_INR, D_IN, N_X, 0, 1);
    }

    // ---- stream s2 (lat branch) ----
    layernorm_kernel<<<B_ * M_LAT, 256, 0, s2>>>(lat, lnh, ln_l_g, ln_l_b, D_LAT);
    wsplit_kernel<<<(D_INR * D_LAT / 4 + 255) / 256, 256, 0, s2>>>(
        (const float4*)Wq, (uint32_t*)wqh, (uint32_t*)wql, D_INR * D_LAT / 4);
    wsplit_kernel<<<(2 * D_INR * D_LAT / 4 + 255) / 256, 256, 0, s2>>>(
        (const float4*)Wlkv, (uint32_t*)wlkvh, (uint32_t*)wlkvl, 2 * D_INR * D_LAT / 4);
    wsplit_kernel<<<(D_LAT * D_INR / 4 + 255) / 256, 256, 0, s2>>>(
        (const float4*)Wo, (uint32_t*)woh, (uint32_t*)wol, D_LAT * D_INR / 4);
    {
        dim3 g(D_INR / 128, (B_ * M_LAT) / 128);
        gemm_mma_kernel<<<g, 256, GEMM_SMEM, s2>>>(lnh, wqh, wql, nullptr, nullptr, qn_g,
                                                   Qhp, Qlp, nullptr, nullptr,
                                                   B_ * M_LAT, D_INR, D_LAT, M_LAT, 0, 2);
    }
    {
        dim3 g((2 * D_INR) / 128, (B_ * M_LAT) / 128);
        gemm_mma_kernel<<<g, 256, GEMM_SMEM, s2>>>(lnh, wlkvh, wlkvl, nullptr, nullptr, kn_g,
                                                   Khp, Klp, Vhp, Vlp,
                                                   B_ * M_LAT, 2 * D_INR, D_LAT, M_LAT, N_X, 1);
    }

    // ---- join ----
    cudaEventRecord(evJ, s2);
    cudaStreamWaitEvent(0, evJ, 0);

    // ---- stream 0: attention -> output projection ----
    {
        dim3 g(M_LAT / QTILE, HEADS, B_);
        attn_mma_kernel<<<g, 128, ATT_SMEM>>>(Qhp, Qlp, Khp, Klp, Vhp, Vlp, mask, atth);
    }
    {
        dim3 g(D_LAT / 128, (B_ * M_LAT) / 128);
        gemm_mma_kernel<<<g, 256, GEMM_SMEM>>>(atth, woh, wol, bo, outp, nullptr,
                                               nullptr, nullptr, nullptr, nullptr,
                                               B_ * M_LAT, D_LAT, D_INR, 0, 0, 0);
    }
}